// round 3
// baseline (speedup 1.0000x reference)
#include <cuda_runtime.h>
#include <cuda_bf16.h>
#include <cstdint>

#define S_DIM 128
#define R_DIM 256
#define CM    256
#define H_DIM 32
#define CZ    128
#define LN_EPS 1e-5f
#define EPS_N  1e-3f

// Scratch: projected activations, transposed to [R][S][H] for the tile kernel.
__device__ float g_aT[R_DIM * S_DIM * H_DIM];   // 4 MB
__device__ float g_bT[R_DIM * S_DIM * H_DIM];   // 4 MB
__device__ float g_norm[R_DIM * R_DIM];         // 256 KB

// ---------------------------------------------------------------------------
// Kernel 1: fused LayerNorm + projection + mask, writes transposed [i][s][h].
// One warp per (s,i) row. which==0 -> g_aT, which==1 -> g_bT.
// ---------------------------------------------------------------------------
__global__ void __launch_bounds__(256) lnproj_kernel(
    const float* __restrict__ m,      // [S,R,CM]
    const float* __restrict__ mask,   // [S,R]
    const float* __restrict__ lnw,
    const float* __restrict__ lnb,
    const float* __restrict__ w,      // [CM,H]
    const float* __restrict__ bias,   // [H]
    int which)
{
    __shared__ float xs[8][CM];
    const int warp = threadIdx.x >> 5;
    const int lane = threadIdx.x & 31;
    const int q = blockIdx.x * 8 + warp;          // row index in [0, S*R)
    const int s = q >> 8;                         // R=256
    const int i = q & 255;

    const float* row = m + (size_t)q * CM;
    float x[8];
    float sum = 0.f;
#pragma unroll
    for (int k = 0; k < 8; k++) { x[k] = row[lane + 32 * k]; sum += x[k]; }
#pragma unroll
    for (int o = 16; o; o >>= 1) sum += __shfl_xor_sync(0xffffffffu, sum, o);
    const float mu = sum * (1.f / CM);

    float vs = 0.f;
#pragma unroll
    for (int k = 0; k < 8; k++) { float d = x[k] - mu; vs += d * d; }
#pragma unroll
    for (int o = 16; o; o >>= 1) vs += __shfl_xor_sync(0xffffffffu, vs, o);
    const float rstd = rsqrtf(vs * (1.f / CM) + LN_EPS);

#pragma unroll
    for (int k = 0; k < 8; k++) {
        int c = lane + 32 * k;
        xs[warp][c] = (x[k] - mu) * rstd * lnw[c] + lnb[c];
    }
    __syncwarp();

    const float mk = mask[q];
    const int h = lane;
    float acc = bias[h];
#pragma unroll 8
    for (int c = 0; c < CM; c++) acc += xs[warp][c] * w[c * H_DIM + h];
    acc *= mk;

    float* dst = which ? g_bT : g_aT;
    dst[((size_t)i * S_DIM + s) * H_DIM + h] = acc;
}

// ---------------------------------------------------------------------------
// Kernel 2: norm[i][j] = sum_s mask1[s,i]*mask2[s,j] + EPS
// ---------------------------------------------------------------------------
__global__ void __launch_bounds__(256) normk_kernel(
    const float* __restrict__ mask1, const float* __restrict__ mask2)
{
    const int i = blockIdx.x;
    const int j = threadIdx.x;
    float sum = 0.f;
#pragma unroll 4
    for (int s = 0; s < S_DIM; s++)
        sum += mask1[s * R_DIM + i] * mask2[s * R_DIM + j];
    g_norm[i * R_DIM + j] = sum + EPS_N;
}

// ---------------------------------------------------------------------------
// Kernel 3: fused outer-product accumulation + w_out projection.
// Grid (64,64): CTA(bj,bi) owns the 4x4 (i,j) tile [bi*4..+4) x [bj*4..+4).
// Phase 1: each thread owns one pair p=(di,dj) and a 2x32 (c,e) accumulator.
// Phase 2: TWO passes of 8 pairs each through a 32 KB static smem buffer
//          (stays under the 48 KB default limit -> no cudaFuncSetAttribute).
// ---------------------------------------------------------------------------
__global__ void __launch_bounds__(256) outer_kernel(
    const float* __restrict__ w_out,   // [1024, CZ]
    const float* __restrict__ b_out,   // [CZ]
    float* __restrict__ out)           // [R, R, CZ]
{
    __shared__ float buf[8192];        // 32 KB
    const int t = threadIdx.x;
    const int bi = blockIdx.y, bj = blockIdx.x;

    const int pair = t >> 4;           // 0..15
    const int di = pair >> 2, dj = pair & 3;
    const int c0 = (t & 15) * 2;       // this thread owns c0, c0+1; all e

    float acc0[32], acc1[32];
#pragma unroll
    for (int e = 0; e < 32; e++) { acc0[e] = 0.f; acc1[e] = 0.f; }

    // phase 1: stream s in chunks of 32
    for (int s0 = 0; s0 < S_DIM; s0 += 32) {
        // cooperative load: a chunk -> buf[0..4095], b chunk -> buf[4096..8191]
#pragma unroll
        for (int r = 0; r < 4; r++) {
            int e4 = (t + 256 * r) * 4;            // element index within chunk
            int sc = e4 >> 7;
            int rem = e4 & 127;
            int ld = rem >> 5;                     // di / dj of source row
            int h = rem & 31;
            size_t srcA = ((size_t)(bi * 4 + ld) * S_DIM + (s0 + sc)) * H_DIM + h;
            size_t srcB = ((size_t)(bj * 4 + ld) * S_DIM + (s0 + sc)) * H_DIM + h;
            *(float4*)&buf[e4]        = *(const float4*)&g_aT[srcA];
            *(float4*)&buf[4096 + e4] = *(const float4*)&g_bT[srcB];
        }
        __syncthreads();

#pragma unroll 4
        for (int sc = 0; sc < 32; sc++) {
            const float2 a2 = *(const float2*)&buf[sc * 128 + di * 32 + c0];
            const float4* bp = (const float4*)&buf[4096 + sc * 128 + dj * 32];
#pragma unroll
            for (int e4 = 0; e4 < 8; e4++) {
                float4 bv = bp[e4];
                acc0[e4 * 4 + 0] += a2.x * bv.x;
                acc0[e4 * 4 + 1] += a2.x * bv.y;
                acc0[e4 * 4 + 2] += a2.x * bv.z;
                acc0[e4 * 4 + 3] += a2.x * bv.w;
                acc1[e4 * 4 + 0] += a2.y * bv.x;
                acc1[e4 * 4 + 1] += a2.y * bv.y;
                acc1[e4 * 4 + 2] += a2.y * bv.z;
                acc1[e4 * 4 + 3] += a2.y * bv.w;
            }
        }
        __syncthreads();
    }

    // phase 2: two passes of 8 pairs each (32 KB staging per pass)
    for (int hp = 0; hp < 2; hp++) {
        // stage this half's outer tiles: buf[lp*1024 + c*32 + e]
        if ((pair >> 3) == hp) {
            const int lp = pair & 7;
#pragma unroll
            for (int e4 = 0; e4 < 8; e4++) {
                *(float4*)&buf[lp * 1024 + c0 * 32 + e4 * 4]       = *(float4*)&acc0[e4 * 4];
                *(float4*)&buf[lp * 1024 + (c0 + 1) * 32 + e4 * 4] = *(float4*)&acc1[e4 * 4];
            }
        }
        __syncthreads();

        // compute: 8 pairs x 32 threads; each thread does 4 z-outputs
        const int lp2 = t >> 5;               // 0..7
        const int p2  = hp * 8 + lp2;
        const int z0  = (t & 31) * 4;

        float zacc[4];
#pragma unroll
        for (int k = 0; k < 4; k++) zacc[k] = b_out[z0 + k];

        const float4* op4 = (const float4*)&buf[lp2 * 1024];
#pragma unroll 2
        for (int m4 = 0; m4 < 256; m4++) {
            float4 ov = op4[m4];
            float4 wv0 = *(const float4*)(w_out + (m4 * 4 + 0) * CZ + z0);
            float4 wv1 = *(const float4*)(w_out + (m4 * 4 + 1) * CZ + z0);
            float4 wv2 = *(const float4*)(w_out + (m4 * 4 + 2) * CZ + z0);
            float4 wv3 = *(const float4*)(w_out + (m4 * 4 + 3) * CZ + z0);
            zacc[0] += ov.x * wv0.x + ov.y * wv1.x + ov.z * wv2.x + ov.w * wv3.x;
            zacc[1] += ov.x * wv0.y + ov.y * wv1.y + ov.z * wv2.y + ov.w * wv3.y;
            zacc[2] += ov.x * wv0.z + ov.y * wv1.z + ov.z * wv2.z + ov.w * wv3.z;
            zacc[3] += ov.x * wv0.w + ov.y * wv1.w + ov.z * wv2.w + ov.w * wv3.w;
        }

        const int i = bi * 4 + (p2 >> 2);
        const int j = bj * 4 + (p2 & 3);
        const float inv_n = 1.f / g_norm[i * R_DIM + j];

        float4 o;
        o.x = zacc[0] * inv_n; o.y = zacc[1] * inv_n;
        o.z = zacc[2] * inv_n; o.w = zacc[3] * inv_n;
        *(float4*)(out + ((size_t)i * R_DIM + j) * CZ + z0) = o;

        __syncthreads();   // buf reused next pass
    }
}

// ---------------------------------------------------------------------------
extern "C" void kernel_launch(void* const* d_in, const int* in_sizes, int n_in,
                              void* d_out, int out_size)
{
    const float* m_1    = (const float*)d_in[0];
    const float* m_2    = (const float*)d_in[1];
    const float* mask_1 = (const float*)d_in[2];
    const float* mask_2 = (const float*)d_in[3];
    const float* ln1_w  = (const float*)d_in[4];
    const float* ln1_b  = (const float*)d_in[5];
    const float* ln2_w  = (const float*)d_in[6];
    const float* ln2_b  = (const float*)d_in[7];
    const float* w1     = (const float*)d_in[8];
    const float* b1     = (const float*)d_in[9];
    const float* w2     = (const float*)d_in[10];
    const float* b2     = (const float*)d_in[11];
    const float* w_out  = (const float*)d_in[12];
    const float* b_out  = (const float*)d_in[13];
    float* out = (float*)d_out;

    lnproj_kernel<<<(S_DIM * R_DIM) / 8, 256>>>(m_1, mask_1, ln1_w, ln1_b, w1, b1, 0);
    lnproj_kernel<<<(S_DIM * R_DIM) / 8, 256>>>(m_2, mask_2, ln2_w, ln2_b, w2, b2, 1);
    normk_kernel<<<R_DIM, R_DIM>>>(mask_1, mask_2);
    outer_kernel<<<dim3(64, 64), 256>>>(w_out, b_out, out);
}

// round 5
// speedup vs baseline: 5.8781x; 5.8781x over previous
#include <cuda_runtime.h>
#include <cuda_bf16.h>
#include <cstdint>

#define S_DIM 128
#define R_DIM 256
#define CM    256
#define H_DIM 32
#define CZ    128
#define LN_EPS 1e-5f
#define EPS_N  1e-3f

// GEMM1 operands: [8192, 128] bf16, row-major (m=(i*32+c), k=s)
__device__ __nv_bfloat16 gAh[8192 * 128];
__device__ __nv_bfloat16 gAl[8192 * 128];
__device__ __nv_bfloat16 gBh[8192 * 128];
__device__ __nv_bfloat16 gBl[8192 * 128];
// GEMM1 output / GEMM2 A: [(i,j)=65536, (c,e)=1024] bf16 hi/lo (128 MB each)
__device__ __nv_bfloat16 gOh[65536 * 1024];
__device__ __nv_bfloat16 gOl[65536 * 1024];
// GEMM2 B: w_out transposed + split: [128 z][1024 k]
__device__ __nv_bfloat16 gWh[128 * 1024];
__device__ __nv_bfloat16 gWl[128 * 1024];
__device__ float g_norm[R_DIM * R_DIM];

// ---------------------------------------------------------------------------
// helpers
// ---------------------------------------------------------------------------
__device__ __forceinline__ uint32_t smem_u32(const void* p) {
    uint32_t a;
    asm("{ .reg .u64 t; cvta.to.shared.u64 t, %1; cvt.u32.u64 %0, t; }" : "=r"(a) : "l"(p));
    return a;
}
#define SWZ128(o) ((o) ^ (((o) >> 3) & 0x70))
#define CP_ASYNC16(dst, src) asm volatile("cp.async.cg.shared.global [%0], [%1], 16;" :: "r"(dst), "l"(src))
#define CP_COMMIT()          asm volatile("cp.async.commit_group;" ::: "memory")
#define CP_WAIT(n)           asm volatile("cp.async.wait_group %0;" :: "n"(n) : "memory")

__device__ __forceinline__ void ldsm_x4(uint32_t* r, uint32_t addr) {
    asm volatile("ldmatrix.sync.aligned.m8n8.x4.shared.b16 {%0,%1,%2,%3}, [%4];"
                 : "=r"(r[0]), "=r"(r[1]), "=r"(r[2]), "=r"(r[3]) : "r"(addr));
}
__device__ __forceinline__ void mma_bf16(float* d, const uint32_t* a, const uint32_t* b) {
    asm volatile(
        "mma.sync.aligned.m16n8k16.row.col.f32.bf16.bf16.f32 "
        "{%0,%1,%2,%3}, {%4,%5,%6,%7}, {%8,%9}, {%0,%1,%2,%3};"
        : "+f"(d[0]), "+f"(d[1]), "+f"(d[2]), "+f"(d[3])
        : "r"(a[0]), "r"(a[1]), "r"(a[2]), "r"(a[3]),
          "r"(b[0]), "r"(b[1]));
}

// ---------------------------------------------------------------------------
// Kernel 1: LN + projection + mask -> bf16 hi/lo at [(i*32+h)][s]
// ---------------------------------------------------------------------------
__global__ void __launch_bounds__(256) lnproj_kernel(
    const float* __restrict__ m, const float* __restrict__ mask,
    const float* __restrict__ lnw, const float* __restrict__ lnb,
    const float* __restrict__ w, const float* __restrict__ bias, int which)
{
    __shared__ float xs[8][CM];
    const int warp = threadIdx.x >> 5, lane = threadIdx.x & 31;
    const int q = blockIdx.x * 8 + warp;
    const int s = q >> 8, i = q & 255;

    const float* row = m + (size_t)q * CM;
    float x[8], sum = 0.f;
#pragma unroll
    for (int k = 0; k < 8; k++) { x[k] = row[lane + 32 * k]; sum += x[k]; }
#pragma unroll
    for (int o = 16; o; o >>= 1) sum += __shfl_xor_sync(0xffffffffu, sum, o);
    const float mu = sum * (1.f / CM);
    float vs = 0.f;
#pragma unroll
    for (int k = 0; k < 8; k++) { float d = x[k] - mu; vs += d * d; }
#pragma unroll
    for (int o = 16; o; o >>= 1) vs += __shfl_xor_sync(0xffffffffu, vs, o);
    const float rstd = rsqrtf(vs * (1.f / CM) + LN_EPS);
#pragma unroll
    for (int k = 0; k < 8; k++) {
        int c = lane + 32 * k;
        xs[warp][c] = (x[k] - mu) * rstd * lnw[c] + lnb[c];
    }
    __syncwarp();

    const float mk = mask[q];
    const int h = lane;
    float acc = bias[h];
#pragma unroll 8
    for (int c = 0; c < CM; c++) acc += xs[warp][c] * w[c * H_DIM + h];
    acc *= mk;

    __nv_bfloat16 hv = __float2bfloat16(acc);
    __nv_bfloat16 lv = __float2bfloat16(acc - __bfloat162float(hv));
    size_t dst = ((size_t)i * 32 + h) * 128 + s;
    if (which == 0) { gAh[dst] = hv; gAl[dst] = lv; }
    else            { gBh[dst] = hv; gBl[dst] = lv; }
}

// ---------------------------------------------------------------------------
// Kernel 2: norm; Kernel 3: w_out transpose/split
// ---------------------------------------------------------------------------
__global__ void __launch_bounds__(256) normk_kernel(
    const float* __restrict__ mask1, const float* __restrict__ mask2)
{
    const int i = blockIdx.x, j = threadIdx.x;
    float sum = 0.f;
#pragma unroll 4
    for (int s = 0; s < S_DIM; s++)
        sum += mask1[s * R_DIM + i] * mask2[s * R_DIM + j];
    g_norm[i * R_DIM + j] = sum + EPS_N;
}

__global__ void __launch_bounds__(128) wsplit_kernel(const float* __restrict__ w_out)
{
    const int k = blockIdx.x, n = threadIdx.x;   // k<1024, n<128
    float v = w_out[k * CZ + n];
    __nv_bfloat16 hv = __float2bfloat16(v);
    gWh[n * 1024 + k] = hv;
    gWl[n * 1024 + k] = __float2bfloat16(v - __bfloat162float(hv));
}

// ---------------------------------------------------------------------------
// GEMM building blocks. K-chunk = 64 elems (128 B rows, SW128 swizzle).
// Buffer layout: Ah[128][64] | Al | Bh | Bl (16 KB each, 64 KB total), x2.
// ---------------------------------------------------------------------------
__device__ __forceinline__ void load_chunk_async(
    uint32_t sbuf,
    const __nv_bfloat16* Ah, const __nv_bfloat16* Al, int sA, int m0,
    const __nv_bfloat16* Bh, const __nv_bfloat16* Bl, int sB, int n0,
    int k0, int t)
{
#pragma unroll
    for (int it = 0; it < 16; it++) {
        int id = it * 256 + t;           // 4096 16B-chunks
        int tile = id >> 10;
        int rem = id & 1023;
        int r = rem >> 3;
        int c8 = (rem & 7) * 8;
        const __nv_bfloat16* src;
        if (tile == 0)      src = Ah + (size_t)(m0 + r) * sA + k0 + c8;
        else if (tile == 1) src = Al + (size_t)(m0 + r) * sA + k0 + c8;
        else if (tile == 2) src = Bh + (size_t)(n0 + r) * sB + k0 + c8;
        else                src = Bl + (size_t)(n0 + r) * sB + k0 + c8;
        uint32_t off = (uint32_t)(r * 128 + c8 * 2);
        CP_ASYNC16(sbuf + tile * 16384 + SWZ128(off), src);
    }
}

__device__ __forceinline__ void compute_chunk(
    uint32_t sbuf, int wm0, int wn0, int lane, float (*acc)[4][4])
{
    const int quad = lane >> 3, r8 = lane & 7;
#pragma unroll
    for (int ks = 0; ks < 4; ks++) {
        const int kb = ks * 32;
        uint32_t ah[4][4], al[4][4];
#pragma unroll
        for (int mf = 0; mf < 4; mf++) {
            int row = wm0 + mf * 16 + (quad & 1) * 8 + r8;
            int kbyte = kb + (quad >> 1) * 16;
            uint32_t off = SWZ128((uint32_t)(row * 128 + kbyte));
            ldsm_x4(ah[mf], sbuf + off);
            ldsm_x4(al[mf], sbuf + 16384 + off);
        }
        uint32_t bh[4][2], bl[4][2];
#pragma unroll
        for (int nb = 0; nb < 2; nb++) {
            int row = wn0 + nb * 16 + (quad >> 1) * 8 + r8;
            int kbyte = kb + (quad & 1) * 16;
            uint32_t off = SWZ128((uint32_t)(row * 128 + kbyte));
            uint32_t r4[4];
            ldsm_x4(r4, sbuf + 32768 + off);
            bh[nb * 2][0] = r4[0]; bh[nb * 2][1] = r4[1];
            bh[nb * 2 + 1][0] = r4[2]; bh[nb * 2 + 1][1] = r4[3];
            ldsm_x4(r4, sbuf + 49152 + off);
            bl[nb * 2][0] = r4[0]; bl[nb * 2][1] = r4[1];
            bl[nb * 2 + 1][0] = r4[2]; bl[nb * 2 + 1][1] = r4[3];
        }
#pragma unroll
        for (int mf = 0; mf < 4; mf++)
#pragma unroll
            for (int nf = 0; nf < 4; nf++) {
                mma_bf16(acc[mf][nf], ah[mf], bh[nf]);
                mma_bf16(acc[mf][nf], ah[mf], bl[nf]);
                mma_bf16(acc[mf][nf], al[mf], bh[nf]);
            }
    }
}

__device__ __forceinline__ void run_mainloop(
    uint32_t sb,
    const __nv_bfloat16* Ah, const __nv_bfloat16* Al, int sA, int m0,
    const __nv_bfloat16* Bh, const __nv_bfloat16* Bl, int sB, int n0,
    int Kc, int t, int wm0, int wn0, int lane, float (*acc)[4][4])
{
    load_chunk_async(sb, Ah, Al, sA, m0, Bh, Bl, sB, n0, 0, t);
    CP_COMMIT();
    for (int k = 0; k < Kc; k++) {
        if (k + 1 < Kc) {
            load_chunk_async(sb + ((k + 1) & 1) * 65536, Ah, Al, sA, m0,
                             Bh, Bl, sB, n0, (k + 1) * 64, t);
            CP_COMMIT();
            CP_WAIT(1);
        } else {
            CP_WAIT(0);
        }
        __syncthreads();
        compute_chunk(sb + (k & 1) * 65536, wm0, wn0, lane, acc);
        __syncthreads();
    }
}

// ---------------------------------------------------------------------------
// GEMM1: outer = A·B^T, epilogue splits fp32 -> bf16 hi/lo in (i,j) layout.
// ---------------------------------------------------------------------------
__global__ void __launch_bounds__(256, 1) gemm1_kernel()
{
    extern __shared__ char dsm[];
    const int t = threadIdx.x, wid = t >> 5, lane = t & 31;
    const int m0 = blockIdx.y * 128, n0 = blockIdx.x * 128;
    const int wm0 = (wid >> 2) * 64, wn0 = (wid & 3) * 32;
    uint32_t sb = smem_u32(dsm);

    float acc[4][4][4];
#pragma unroll
    for (int a = 0; a < 4; a++)
#pragma unroll
        for (int b = 0; b < 4; b++)
#pragma unroll
            for (int c = 0; c < 4; c++) acc[a][b][c] = 0.f;

    run_mainloop(sb, gAh, gAl, 128, m0, gBh, gBl, 128, n0, 2, t, wm0, wn0, lane, acc);

#pragma unroll
    for (int mf = 0; mf < 4; mf++)
#pragma unroll
        for (int nf = 0; nf < 4; nf++)
#pragma unroll
            for (int half = 0; half < 2; half++) {
                int gm = m0 + wm0 + mf * 16 + (lane >> 2) + half * 8;
                int gn = n0 + wn0 + nf * 8 + (lane & 3) * 2;
                float v0 = acc[mf][nf][half * 2 + 0];
                float v1 = acc[mf][nf][half * 2 + 1];
                int i = gm >> 5, c = gm & 31, j = gn >> 5, e = gn & 31;
                size_t dst = (((size_t)i * 256 + j) << 10) + (c << 5) + e;
                __nv_bfloat16 h0 = __float2bfloat16(v0);
                __nv_bfloat16 h1 = __float2bfloat16(v1);
                __nv_bfloat162 hp; hp.x = h0; hp.y = h1;
                __nv_bfloat162 lp;
                lp.x = __float2bfloat16(v0 - __bfloat162float(h0));
                lp.y = __float2bfloat16(v1 - __bfloat162float(h1));
                *(__nv_bfloat162*)(gOh + dst) = hp;
                *(__nv_bfloat162*)(gOl + dst) = lp;
            }
}

// ---------------------------------------------------------------------------
// GEMM2: z = gO · gW^T + b_out, scaled by 1/norm.  grid 512.
// ---------------------------------------------------------------------------
__global__ void __launch_bounds__(256, 1) gemm2_kernel(
    const float* __restrict__ b_out, float* __restrict__ out)
{
    extern __shared__ char dsm[];
    const int t = threadIdx.x, wid = t >> 5, lane = t & 31;
    const int m0 = blockIdx.x * 128;
    const int wm0 = (wid >> 2) * 64, wn0 = (wid & 3) * 32;
    uint32_t sb = smem_u32(dsm);

    float acc[4][4][4];
#pragma unroll
    for (int a = 0; a < 4; a++)
#pragma unroll
        for (int b = 0; b < 4; b++)
#pragma unroll
            for (int c = 0; c < 4; c++) acc[a][b][c] = 0.f;

    run_mainloop(sb, gOh, gOl, 1024, m0, gWh, gWl, 1024, 0, 16, t, wm0, wn0, lane, acc);

#pragma unroll
    for (int mf = 0; mf < 4; mf++)
#pragma unroll
        for (int half = 0; half < 2; half++) {
            int gm = m0 + wm0 + mf * 16 + (lane >> 2) + half * 8;
            const float invn = 1.f / g_norm[gm];
#pragma unroll
            for (int nf = 0; nf < 4; nf++) {
                int gn = wn0 + nf * 8 + (lane & 3) * 2;
                float2 o;
                o.x = (acc[mf][nf][half * 2 + 0] + __ldg(b_out + gn)) * invn;
                o.y = (acc[mf][nf][half * 2 + 1] + __ldg(b_out + gn + 1)) * invn;
                *(float2*)(out + (size_t)gm * CZ + gn) = o;
            }
        }
}

// ---------------------------------------------------------------------------
extern "C" void kernel_launch(void* const* d_in, const int* in_sizes, int n_in,
                              void* d_out, int out_size)
{
    const float* m_1    = (const float*)d_in[0];
    const float* m_2    = (const float*)d_in[1];
    const float* mask_1 = (const float*)d_in[2];
    const float* mask_2 = (const float*)d_in[3];
    const float* ln1_w  = (const float*)d_in[4];
    const float* ln1_b  = (const float*)d_in[5];
    const float* ln2_w  = (const float*)d_in[6];
    const float* ln2_b  = (const float*)d_in[7];
    const float* w1     = (const float*)d_in[8];
    const float* b1     = (const float*)d_in[9];
    const float* w2     = (const float*)d_in[10];
    const float* b2     = (const float*)d_in[11];
    const float* w_out  = (const float*)d_in[12];
    const float* b_out  = (const float*)d_in[13];
    float* out = (float*)d_out;

    cudaFuncSetAttribute(gemm1_kernel,
                         cudaFuncAttributeMaxDynamicSharedMemorySize, 131072);
    cudaFuncSetAttribute(gemm2_kernel,
                         cudaFuncAttributeMaxDynamicSharedMemorySize, 131072);

    lnproj_kernel<<<(S_DIM * R_DIM) / 8, 256>>>(m_1, mask_1, ln1_w, ln1_b, w1, b1, 0);
    lnproj_kernel<<<(S_DIM * R_DIM) / 8, 256>>>(m_2, mask_2, ln2_w, ln2_b, w2, b2, 1);
    normk_kernel<<<R_DIM, R_DIM>>>(mask_1, mask_2);
    wsplit_kernel<<<1024, 128>>>(w_out);
    gemm1_kernel<<<dim3(64, 64), 256, 131072>>>();
    gemm2_kernel<<<512, 256, 131072>>>(b_out, out);
}

// round 6
// speedup vs baseline: 6.0973x; 1.0373x over previous
#include <cuda_runtime.h>
#include <cuda_bf16.h>
#include <cuda_fp16.h>
#include <cstdint>

#define S_DIM 128
#define R_DIM 256
#define CM    256
#define H_DIM 32
#define CZ    128
#define LN_EPS 1e-5f
#define EPS_N  1e-3f

// GEMM1 operands: [8192, 128] bf16, row-major (m=(i*32+c), k=s)
__device__ __nv_bfloat16 gAh[8192 * 128];
__device__ __nv_bfloat16 gAl[8192 * 128];
__device__ __nv_bfloat16 gBh[8192 * 128];
__device__ __nv_bfloat16 gBl[8192 * 128];
// Projection weight: w_out transposed, single fp16: [128 z][1024 k]
__device__ __half gWf[128 * 1024];
__device__ float g_norm[R_DIM * R_DIM];

// ---------------------------------------------------------------------------
// helpers
// ---------------------------------------------------------------------------
__device__ __forceinline__ uint32_t smem_u32(const void* p) {
    uint32_t a;
    asm("{ .reg .u64 t; cvta.to.shared.u64 t, %1; cvt.u32.u64 %0, t; }" : "=r"(a) : "l"(p));
    return a;
}
#define SWZ128(o) ((o) ^ (((o) >> 3) & 0x70))
#define CP_ASYNC16(dst, src) asm volatile("cp.async.cg.shared.global [%0], [%1], 16;" :: "r"(dst), "l"(src))
#define CP_COMMIT()          asm volatile("cp.async.commit_group;" ::: "memory")
#define CP_WAIT(n)           asm volatile("cp.async.wait_group %0;" :: "n"(n) : "memory")

__device__ __forceinline__ void ldsm_x4(uint32_t* r, uint32_t addr) {
    asm volatile("ldmatrix.sync.aligned.m8n8.x4.shared.b16 {%0,%1,%2,%3}, [%4];"
                 : "=r"(r[0]), "=r"(r[1]), "=r"(r[2]), "=r"(r[3]) : "r"(addr));
}
__device__ __forceinline__ void mma_bf16(float* d, const uint32_t* a, const uint32_t* b) {
    asm volatile(
        "mma.sync.aligned.m16n8k16.row.col.f32.bf16.bf16.f32 "
        "{%0,%1,%2,%3}, {%4,%5,%6,%7}, {%8,%9}, {%0,%1,%2,%3};"
        : "+f"(d[0]), "+f"(d[1]), "+f"(d[2]), "+f"(d[3])
        : "r"(a[0]), "r"(a[1]), "r"(a[2]), "r"(a[3]),
          "r"(b[0]), "r"(b[1]));
}
__device__ __forceinline__ void mma_f16(float* d, const uint32_t* a, const uint32_t* b) {
    asm volatile(
        "mma.sync.aligned.m16n8k16.row.col.f32.f16.f16.f32 "
        "{%0,%1,%2,%3}, {%4,%5,%6,%7}, {%8,%9}, {%0,%1,%2,%3};"
        : "+f"(d[0]), "+f"(d[1]), "+f"(d[2]), "+f"(d[3])
        : "r"(a[0]), "r"(a[1]), "r"(a[2]), "r"(a[3]),
          "r"(b[0]), "r"(b[1]));
}

// ---------------------------------------------------------------------------
// Kernel 1: LN + projection + mask -> bf16 hi/lo at [(i*32+h)][s]
// ---------------------------------------------------------------------------
__global__ void __launch_bounds__(256) lnproj_kernel(
    const float* __restrict__ m, const float* __restrict__ mask,
    const float* __restrict__ lnw, const float* __restrict__ lnb,
    const float* __restrict__ w, const float* __restrict__ bias, int which)
{
    __shared__ float xs[8][CM];
    const int warp = threadIdx.x >> 5, lane = threadIdx.x & 31;
    const int q = blockIdx.x * 8 + warp;
    const int s = q >> 8, i = q & 255;

    const float* row = m + (size_t)q * CM;
    float x[8], sum = 0.f;
#pragma unroll
    for (int k = 0; k < 8; k++) { x[k] = row[lane + 32 * k]; sum += x[k]; }
#pragma unroll
    for (int o = 16; o; o >>= 1) sum += __shfl_xor_sync(0xffffffffu, sum, o);
    const float mu = sum * (1.f / CM);
    float vs = 0.f;
#pragma unroll
    for (int k = 0; k < 8; k++) { float d = x[k] - mu; vs += d * d; }
#pragma unroll
    for (int o = 16; o; o >>= 1) vs += __shfl_xor_sync(0xffffffffu, vs, o);
    const float rstd = rsqrtf(vs * (1.f / CM) + LN_EPS);
#pragma unroll
    for (int k = 0; k < 8; k++) {
        int c = lane + 32 * k;
        xs[warp][c] = (x[k] - mu) * rstd * lnw[c] + lnb[c];
    }
    __syncwarp();

    const float mk = mask[q];
    const int h = lane;
    float acc = bias[h];
#pragma unroll 8
    for (int c = 0; c < CM; c++) acc += xs[warp][c] * w[c * H_DIM + h];
    acc *= mk;

    __nv_bfloat16 hv = __float2bfloat16(acc);
    __nv_bfloat16 lv = __float2bfloat16(acc - __bfloat162float(hv));
    size_t dst = ((size_t)i * 32 + h) * 128 + s;
    if (which == 0) { gAh[dst] = hv; gAl[dst] = lv; }
    else            { gBh[dst] = hv; gBl[dst] = lv; }
}

// ---------------------------------------------------------------------------
// Kernel 2: norm; Kernel 3: w_out transpose to fp16
// ---------------------------------------------------------------------------
__global__ void __launch_bounds__(256) normk_kernel(
    const float* __restrict__ mask1, const float* __restrict__ mask2)
{
    const int i = blockIdx.x, j = threadIdx.x;
    float sum = 0.f;
#pragma unroll 4
    for (int s = 0; s < S_DIM; s++)
        sum += mask1[s * R_DIM + i] * mask2[s * R_DIM + j];
    g_norm[i * R_DIM + j] = sum + EPS_N;
}

__global__ void __launch_bounds__(128) wsplit_kernel(const float* __restrict__ w_out)
{
    const int k = blockIdx.x, n = threadIdx.x;   // k<1024, n<128
    gWf[n * 1024 + k] = __float2half_rn(w_out[k * CZ + n]);
}

// ---------------------------------------------------------------------------
// Mainloop building blocks (bf16, 3 products). K-chunk = 64, SW128 tiles.
// Buffer: Ah[128][64] | Al | Bh | Bl (16 KB each, 64 KB), double-buffered.
// ---------------------------------------------------------------------------
__device__ __forceinline__ void load_chunk_async(
    uint32_t sbuf,
    const __nv_bfloat16* Ah, const __nv_bfloat16* Al, int m0,
    const __nv_bfloat16* Bh, const __nv_bfloat16* Bl, int n0,
    int k0, int t)
{
#pragma unroll
    for (int it = 0; it < 16; it++) {
        int id = it * 256 + t;
        int tile = id >> 10;
        int rem = id & 1023;
        int r = rem >> 3;
        int c8 = (rem & 7) * 8;
        const __nv_bfloat16* src;
        if (tile == 0)      src = Ah + (size_t)(m0 + r) * 128 + k0 + c8;
        else if (tile == 1) src = Al + (size_t)(m0 + r) * 128 + k0 + c8;
        else if (tile == 2) src = Bh + (size_t)(n0 + r) * 128 + k0 + c8;
        else                src = Bl + (size_t)(n0 + r) * 128 + k0 + c8;
        uint32_t off = (uint32_t)(r * 128 + c8 * 2);
        CP_ASYNC16(sbuf + tile * 16384 + SWZ128(off), src);
    }
}

__device__ __forceinline__ void compute_chunk(
    uint32_t sbuf, int wm0, int wn0, int lane, float (*acc)[4][4])
{
    const int quad = lane >> 3, r8 = lane & 7;
#pragma unroll
    for (int ks = 0; ks < 4; ks++) {
        const int kb = ks * 32;
        uint32_t ah[4][4], al[4][4];
#pragma unroll
        for (int mf = 0; mf < 4; mf++) {
            int row = wm0 + mf * 16 + (quad & 1) * 8 + r8;
            int kbyte = kb + (quad >> 1) * 16;
            uint32_t off = SWZ128((uint32_t)(row * 128 + kbyte));
            ldsm_x4(ah[mf], sbuf + off);
            ldsm_x4(al[mf], sbuf + 16384 + off);
        }
        uint32_t bh[4][2], bl[4][2];
#pragma unroll
        for (int nb = 0; nb < 2; nb++) {
            int row = wn0 + nb * 16 + (quad >> 1) * 8 + r8;
            int kbyte = kb + (quad & 1) * 16;
            uint32_t off = SWZ128((uint32_t)(row * 128 + kbyte));
            uint32_t r4[4];
            ldsm_x4(r4, sbuf + 32768 + off);
            bh[nb * 2][0] = r4[0]; bh[nb * 2][1] = r4[1];
            bh[nb * 2 + 1][0] = r4[2]; bh[nb * 2 + 1][1] = r4[3];
            ldsm_x4(r4, sbuf + 49152 + off);
            bl[nb * 2][0] = r4[0]; bl[nb * 2][1] = r4[1];
            bl[nb * 2 + 1][0] = r4[2]; bl[nb * 2 + 1][1] = r4[3];
        }
#pragma unroll
        for (int mf = 0; mf < 4; mf++)
#pragma unroll
            for (int nf = 0; nf < 4; nf++) {
                mma_bf16(acc[mf][nf], ah[mf], bh[nf]);
                mma_bf16(acc[mf][nf], ah[mf], bl[nf]);
                mma_bf16(acc[mf][nf], al[mf], bh[nf]);
            }
    }
}

// ---------------------------------------------------------------------------
// Fused kernel: outer tile (mainloop) + w_out projection (epilogue).
// Smem map (131072 B): mainloop buf0 @0, buf1 @65536.
// Epilogue: O-hi @0 (32 KB), O-lo @32768 (32 KB), W buf0 @65536, W buf1 @81920.
// ---------------------------------------------------------------------------
__global__ void __launch_bounds__(256, 1) fused_kernel(
    const float* __restrict__ b_out, float* __restrict__ out)
{
    extern __shared__ char dsm[];
    const int t = threadIdx.x, wid = t >> 5, lane = t & 31;
    const int bi = blockIdx.y, bj = blockIdx.x;
    const int m0 = bi * 128, n0 = bj * 128;
    const int wm0 = (wid >> 2) * 64, wn0 = (wid & 3) * 32;
    const int quad = lane >> 3, r8 = lane & 7;
    uint32_t sb = smem_u32(dsm);

    float acc[4][4][4];
#pragma unroll
    for (int a = 0; a < 4; a++)
#pragma unroll
        for (int b = 0; b < 4; b++)
#pragma unroll
            for (int c = 0; c < 4; c++) acc[a][b][c] = 0.f;

    // ---- mainloop: outer tile = A[128,:]·B[128,:]^T (K=128, 2 chunks) ----
    load_chunk_async(sb, gAh, gAl, m0, gBh, gBl, n0, 0, t);
    CP_COMMIT();
    for (int k = 0; k < 2; k++) {
        if (k + 1 < 2) {
            load_chunk_async(sb + 65536, gAh, gAl, m0, gBh, gBl, n0, 64, t);
            CP_COMMIT();
            CP_WAIT(1);
        } else {
            CP_WAIT(0);
        }
        __syncthreads();
        compute_chunk(sb + (k & 1) * 65536, wm0, wn0, lane, acc);
        __syncthreads();
    }

    // ---- stage outer tile to smem as fp16 hi/lo: [p=16][k=1024] ----
    // addr(p, kbyte) = p*2048 + (kbyte ^ ((p&7)<<4))
#pragma unroll
    for (int mf = 0; mf < 4; mf++)
#pragma unroll
        for (int nf = 0; nf < 4; nf++)
#pragma unroll
            for (int half = 0; half < 2; half++) {
                int gm = wm0 + mf * 16 + (lane >> 2) + half * 8;
                int gn = wn0 + nf * 8 + (lane & 3) * 2;
                float v0 = acc[mf][nf][half * 2 + 0];
                float v1 = acc[mf][nf][half * 2 + 1];
                int p = ((gm >> 5) << 2) | (gn >> 5);
                int k = ((gm & 31) << 5) | (gn & 31);
                __half h0 = __float2half_rn(v0), h1 = __float2half_rn(v1);
                __half2 hp; hp.x = h0; hp.y = h1;
                __half2 lp;
                lp.x = __float2half_rn(v0 - __half2float(h0));
                lp.y = __float2half_rn(v1 - __half2float(h1));
                uint32_t off = (uint32_t)(p * 2048 + ((k * 2) ^ ((p & 7) << 4)));
                *(__half2*)(dsm + off) = hp;
                *(__half2*)(dsm + 32768 + off) = lp;
            }

    // W chunk loader: [128 z rows][64 k] fp16 = 128 B/row, 16 KB tile
    auto loadW = [&](int kc, int buf) {
#pragma unroll
        for (int it = 0; it < 4; it++) {
            int id = it * 256 + t;           // 1024 16B-chunks
            int r = id >> 3, c8 = (id & 7) * 8;
            const __half* src = gWf + (size_t)r * 1024 + kc * 64 + c8;
            uint32_t off = SWZ128((uint32_t)(r * 128 + c8 * 2));
            CP_ASYNC16(sb + 65536 + buf * 16384 + off, src);
        }
    };
    loadW(0, 0);
    CP_COMMIT();
    __syncthreads();   // O visible; W0 in flight

    // ---- projection: z[16][128] = O[16][1024] · W^T (2 fp16 products) ----
    float zacc[2][4] = {{0.f, 0.f, 0.f, 0.f}, {0.f, 0.f, 0.f, 0.f}};
    const int wz0 = wid * 16;
    for (int kc = 0; kc < 16; kc++) {
        if (kc + 1 < 16) {
            loadW(kc + 1, (kc + 1) & 1);
            CP_COMMIT();
            CP_WAIT(1);
        } else {
            CP_WAIT(0);
        }
        __syncthreads();
        uint32_t wbase = sb + 65536 + (kc & 1) * 16384;
#pragma unroll
        for (int ks = 0; ks < 4; ks++) {
            int arow = (quad & 1) * 8 + r8;
            uint32_t akb = (uint32_t)(kc * 128 + ks * 32 + (quad >> 1) * 16);
            uint32_t aoff = (uint32_t)(arow * 2048) + (akb ^ ((uint32_t)(arow & 7) << 4));
            uint32_t ah[4], al[4];
            ldsm_x4(ah, sb + aoff);
            ldsm_x4(al, sb + 32768 + aoff);

            int brow = wz0 + (quad >> 1) * 8 + r8;
            uint32_t bkb = (uint32_t)(ks * 32 + (quad & 1) * 16);
            uint32_t r4[4];
            ldsm_x4(r4, wbase + SWZ128((uint32_t)(brow * 128) + bkb));
            uint32_t b0[2] = {r4[0], r4[1]}, b1[2] = {r4[2], r4[3]};

            mma_f16(zacc[0], ah, b0);
            mma_f16(zacc[0], al, b0);
            mma_f16(zacc[1], ah, b1);
            mma_f16(zacc[1], al, b1);
        }
        __syncthreads();
    }

    // ---- output: add bias, scale by 1/norm ----
#pragma unroll
    for (int nt = 0; nt < 2; nt++)
#pragma unroll
        for (int hp = 0; hp < 2; hp++) {
            int p = (lane >> 2) + hp * 8;
            int i = bi * 4 + (p >> 2), j = bj * 4 + (p & 3);
            float invn = 1.f / g_norm[i * R_DIM + j];
            int z0 = wz0 + nt * 8 + (lane & 3) * 2;
            float2 o;
            o.x = (zacc[nt][hp * 2 + 0] + __ldg(b_out + z0)) * invn;
            o.y = (zacc[nt][hp * 2 + 1] + __ldg(b_out + z0 + 1)) * invn;
            *(float2*)(out + ((size_t)i * R_DIM + j) * CZ + z0) = o;
        }
}

// ---------------------------------------------------------------------------
extern "C" void kernel_launch(void* const* d_in, const int* in_sizes, int n_in,
                              void* d_out, int out_size)
{
    const float* m_1    = (const float*)d_in[0];
    const float* m_2    = (const float*)d_in[1];
    const float* mask_1 = (const float*)d_in[2];
    const float* mask_2 = (const float*)d_in[3];
    const float* ln1_w  = (const float*)d_in[4];
    const float* ln1_b  = (const float*)d_in[5];
    const float* ln2_w  = (const float*)d_in[6];
    const float* ln2_b  = (const float*)d_in[7];
    const float* w1     = (const float*)d_in[8];
    const float* b1     = (const float*)d_in[9];
    const float* w2     = (const float*)d_in[10];
    const float* b2     = (const float*)d_in[11];
    const float* w_out  = (const float*)d_in[12];
    const float* b_out  = (const float*)d_in[13];
    float* out = (float*)d_out;

    cudaFuncSetAttribute(fused_kernel,
                         cudaFuncAttributeMaxDynamicSharedMemorySize, 131072);

    lnproj_kernel<<<(S_DIM * R_DIM) / 8, 256>>>(m_1, mask_1, ln1_w, ln1_b, w1, b1, 0);
    lnproj_kernel<<<(S_DIM * R_DIM) / 8, 256>>>(m_2, mask_2, ln2_w, ln2_b, w2, b2, 1);
    normk_kernel<<<R_DIM, R_DIM>>>(mask_1, mask_2);
    wsplit_kernel<<<1024, 128>>>(w_out);
    fused_kernel<<<dim3(64, 64), 256, 131072>>>(b_out, out);
}

// round 7
// speedup vs baseline: 9.6975x; 1.5905x over previous
#include <cuda_runtime.h>
#include <cuda_bf16.h>
#include <cuda_fp16.h>
#include <cstdint>

#define S_DIM 128
#define R_DIM 256
#define CM    256
#define H_DIM 32
#define CZ    128
#define LN_EPS 1e-5f
#define EPS_N  1e-3f

// GEMM1 operands: [8192, 128] fp16, row-major (m=(i*32+c), k=s)
__device__ __half gAf[8192 * 128];
__device__ __half gBf[8192 * 128];
// Projection weight: w_out transposed, fp16: [128 z][1024 k]
__device__ __half gWf[128 * 1024];
__device__ float g_norm[R_DIM * R_DIM];

// ---------------------------------------------------------------------------
// helpers
// ---------------------------------------------------------------------------
__device__ __forceinline__ uint32_t smem_u32(const void* p) {
    uint32_t a;
    asm("{ .reg .u64 t; cvta.to.shared.u64 t, %1; cvt.u32.u64 %0, t; }" : "=r"(a) : "l"(p));
    return a;
}
#define SWZ128(o) ((o) ^ (((o) >> 3) & 0x70))
#define CP_ASYNC16(dst, src) asm volatile("cp.async.cg.shared.global [%0], [%1], 16;" :: "r"(dst), "l"(src))
#define CP_COMMIT()          asm volatile("cp.async.commit_group;" ::: "memory")
#define CP_WAIT(n)           asm volatile("cp.async.wait_group %0;" :: "n"(n) : "memory")

__device__ __forceinline__ void ldsm_x4(uint32_t* r, uint32_t addr) {
    asm volatile("ldmatrix.sync.aligned.m8n8.x4.shared.b16 {%0,%1,%2,%3}, [%4];"
                 : "=r"(r[0]), "=r"(r[1]), "=r"(r[2]), "=r"(r[3]) : "r"(addr));
}
__device__ __forceinline__ void mma_f16(float* d, const uint32_t* a, const uint32_t* b) {
    asm volatile(
        "mma.sync.aligned.m16n8k16.row.col.f32.f16.f16.f32 "
        "{%0,%1,%2,%3}, {%4,%5,%6,%7}, {%8,%9}, {%0,%1,%2,%3};"
        : "+f"(d[0]), "+f"(d[1]), "+f"(d[2]), "+f"(d[3])
        : "r"(a[0]), "r"(a[1]), "r"(a[2]), "r"(a[3]),
          "r"(b[0]), "r"(b[1]));
}

// ---------------------------------------------------------------------------
// Kernel 1: LN + projection + mask -> fp16 at [(i*32+h)][s]
// ---------------------------------------------------------------------------
__global__ void __launch_bounds__(256) lnproj_kernel(
    const float* __restrict__ m, const float* __restrict__ mask,
    const float* __restrict__ lnw, const float* __restrict__ lnb,
    const float* __restrict__ w, const float* __restrict__ bias, int which)
{
    __shared__ float xs[8][CM];
    const int warp = threadIdx.x >> 5, lane = threadIdx.x & 31;
    const int q = blockIdx.x * 8 + warp;
    const int s = q >> 8, i = q & 255;

    const float* row = m + (size_t)q * CM;
    float x[8], sum = 0.f;
#pragma unroll
    for (int k = 0; k < 8; k++) { x[k] = row[lane + 32 * k]; sum += x[k]; }
#pragma unroll
    for (int o = 16; o; o >>= 1) sum += __shfl_xor_sync(0xffffffffu, sum, o);
    const float mu = sum * (1.f / CM);
    float vs = 0.f;
#pragma unroll
    for (int k = 0; k < 8; k++) { float d = x[k] - mu; vs += d * d; }
#pragma unroll
    for (int o = 16; o; o >>= 1) vs += __shfl_xor_sync(0xffffffffu, vs, o);
    const float rstd = rsqrtf(vs * (1.f / CM) + LN_EPS);
#pragma unroll
    for (int k = 0; k < 8; k++) {
        int c = lane + 32 * k;
        xs[warp][c] = (x[k] - mu) * rstd * lnw[c] + lnb[c];
    }
    __syncwarp();

    const float mk = mask[q];
    const int h = lane;
    float acc = bias[h];
#pragma unroll 8
    for (int c = 0; c < CM; c++) acc += xs[warp][c] * w[c * H_DIM + h];
    acc *= mk;

    size_t dst = ((size_t)i * 32 + h) * 128 + s;
    if (which == 0) gAf[dst] = __float2half_rn(acc);
    else            gBf[dst] = __float2half_rn(acc);
}

// ---------------------------------------------------------------------------
// Kernel 2: prep = norm matrix + w_out transpose to fp16 (merged)
// grid 256 x 256 threads
// ---------------------------------------------------------------------------
__global__ void __launch_bounds__(256) prep_kernel(
    const float* __restrict__ mask1, const float* __restrict__ mask2,
    const float* __restrict__ w_out)
{
    const int i = blockIdx.x, j = threadIdx.x;
    float sum = 0.f;
#pragma unroll 4
    for (int s = 0; s < S_DIM; s++)
        sum += mask1[s * R_DIM + i] * mask2[s * R_DIM + j];
    g_norm[i * R_DIM + j] = sum + EPS_N;

    // w transpose: 131072 elements over 65536 threads -> 2 each
    int idx = blockIdx.x * 256 + threadIdx.x;
#pragma unroll
    for (int r = 0; r < 2; r++) {
        int id = idx + r * 65536;
        int k = id >> 7, n = id & 127;
        gWf[n * 1024 + k] = __float2half_rn(w_out[k * CZ + n]);
    }
}

// ---------------------------------------------------------------------------
// Mainloop blocks (fp16 single product). K-chunk = 64 elems, SW128.
// Chunk buffer: A[128][64] (16 KB) | B[128][64] (16 KB) = 32 KB, x2 buffers.
// ---------------------------------------------------------------------------
__device__ __forceinline__ void load_chunk_async(
    uint32_t sbuf, int m0, int n0, int k0, int t)
{
#pragma unroll
    for (int it = 0; it < 8; it++) {
        int id = it * 256 + t;           // 2048 16B-chunks
        int tile = id >> 10;
        int rem = id & 1023;
        int r = rem >> 3;
        int c8 = (rem & 7) * 8;
        const __half* src = (tile == 0)
            ? gAf + (size_t)(m0 + r) * 128 + k0 + c8
            : gBf + (size_t)(n0 + r) * 128 + k0 + c8;
        uint32_t off = (uint32_t)(r * 128 + c8 * 2);
        CP_ASYNC16(sbuf + tile * 16384 + SWZ128(off), src);
    }
}

__device__ __forceinline__ void compute_chunk(
    uint32_t sbuf, int wm0, int wn0, int lane, float (*acc)[4][4])
{
    const int quad = lane >> 3, r8 = lane & 7;
#pragma unroll
    for (int ks = 0; ks < 4; ks++) {
        const int kb = ks * 32;
        uint32_t a4[4][4];
#pragma unroll
        for (int mf = 0; mf < 4; mf++) {
            int row = wm0 + mf * 16 + (quad & 1) * 8 + r8;
            int kbyte = kb + (quad >> 1) * 16;
            ldsm_x4(a4[mf], sbuf + SWZ128((uint32_t)(row * 128 + kbyte)));
        }
        uint32_t b4[4][2];
#pragma unroll
        for (int nb = 0; nb < 2; nb++) {
            int row = wn0 + nb * 16 + (quad >> 1) * 8 + r8;
            int kbyte = kb + (quad & 1) * 16;
            uint32_t r4[4];
            ldsm_x4(r4, sbuf + 16384 + SWZ128((uint32_t)(row * 128 + kbyte)));
            b4[nb * 2][0] = r4[0]; b4[nb * 2][1] = r4[1];
            b4[nb * 2 + 1][0] = r4[2]; b4[nb * 2 + 1][1] = r4[3];
        }
#pragma unroll
        for (int mf = 0; mf < 4; mf++)
#pragma unroll
            for (int nf = 0; nf < 4; nf++)
                mma_f16(acc[mf][nf], a4[mf], b4[nf]);
    }
}

// ---------------------------------------------------------------------------
// Fused kernel. Smem (65536 B):
//   mainloop: buf0 @0 (32 KB), buf1 @32768 (32 KB)
//   epilogue: O fp16 [16][1024] @0 (32 KB), W buf0 @32768, W buf1 @49152
// ---------------------------------------------------------------------------
__global__ void __launch_bounds__(256, 2) fused_kernel(
    const float* __restrict__ b_out, float* __restrict__ out)
{
    extern __shared__ char dsm[];
    const int t = threadIdx.x, wid = t >> 5, lane = t & 31;
    const int bi = blockIdx.y, bj = blockIdx.x;
    const int m0 = bi * 128, n0 = bj * 128;
    const int wm0 = (wid >> 2) * 64, wn0 = (wid & 3) * 32;
    const int quad = lane >> 3, r8 = lane & 7;
    uint32_t sb = smem_u32(dsm);

    float acc[4][4][4];
#pragma unroll
    for (int a = 0; a < 4; a++)
#pragma unroll
        for (int b = 0; b < 4; b++)
#pragma unroll
            for (int c = 0; c < 4; c++) acc[a][b][c] = 0.f;

    // ---- mainloop: outer tile = A[128,:]·B[128,:]^T (K=128, 2 chunks) ----
    load_chunk_async(sb, m0, n0, 0, t);
    CP_COMMIT();
    for (int k = 0; k < 2; k++) {
        if (k + 1 < 2) {
            load_chunk_async(sb + 32768, m0, n0, 64, t);
            CP_COMMIT();
            CP_WAIT(1);
        } else {
            CP_WAIT(0);
        }
        __syncthreads();
        compute_chunk(sb + (k & 1) * 32768, wm0, wn0, lane, acc);
        __syncthreads();
    }

    // ---- stage outer tile to smem fp16: [p=16][k=1024] ----
    // addr(p, kbyte) = p*2048 + (kbyte ^ ((p&7)<<4))
#pragma unroll
    for (int mf = 0; mf < 4; mf++)
#pragma unroll
        for (int nf = 0; nf < 4; nf++)
#pragma unroll
            for (int half = 0; half < 2; half++) {
                int gm = wm0 + mf * 16 + (lane >> 2) + half * 8;
                int gn = wn0 + nf * 8 + (lane & 3) * 2;
                int p = ((gm >> 5) << 2) | (gn >> 5);
                int k = ((gm & 31) << 5) | (gn & 31);
                __half2 hp;
                hp.x = __float2half_rn(acc[mf][nf][half * 2 + 0]);
                hp.y = __float2half_rn(acc[mf][nf][half * 2 + 1]);
                uint32_t off = (uint32_t)(p * 2048 + ((k * 2) ^ ((p & 7) << 4)));
                *(__half2*)(dsm + off) = hp;
            }

    // W chunk loader: [128 z rows][64 k] fp16 = 16 KB tile
    auto loadW = [&](int kc, int buf) {
#pragma unroll
        for (int it = 0; it < 4; it++) {
            int id = it * 256 + t;           // 1024 16B-chunks
            int r = id >> 3, c8 = (id & 7) * 8;
            const __half* src = gWf + (size_t)r * 1024 + kc * 64 + c8;
            uint32_t off = SWZ128((uint32_t)(r * 128 + c8 * 2));
            CP_ASYNC16(sb + 32768 + buf * 16384 + off, src);
        }
    };
    loadW(0, 0);
    CP_COMMIT();
    __syncthreads();   // O visible; W0 in flight

    // ---- projection: z[16][128] = O[16][1024] · W^T (single fp16 product) ----
    float zacc[2][4] = {{0.f, 0.f, 0.f, 0.f}, {0.f, 0.f, 0.f, 0.f}};
    const int wz0 = wid * 16;
    for (int kc = 0; kc < 16; kc++) {
        if (kc + 1 < 16) {
            loadW(kc + 1, (kc + 1) & 1);
            CP_COMMIT();
            CP_WAIT(1);
        } else {
            CP_WAIT(0);
        }
        __syncthreads();
        uint32_t wbase = sb + 32768 + (kc & 1) * 16384;
#pragma unroll
        for (int ks = 0; ks < 4; ks++) {
            int arow = (quad & 1) * 8 + r8;
            uint32_t akb = (uint32_t)(kc * 128 + ks * 32 + (quad >> 1) * 16);
            uint32_t aoff = (uint32_t)(arow * 2048) + (akb ^ ((uint32_t)(arow & 7) << 4));
            uint32_t ah[4];
            ldsm_x4(ah, sb + aoff);

            int brow = wz0 + (quad >> 1) * 8 + r8;
            uint32_t bkb = (uint32_t)(ks * 32 + (quad & 1) * 16);
            uint32_t r4[4];
            ldsm_x4(r4, wbase + SWZ128((uint32_t)(brow * 128) + bkb));
            uint32_t b0[2] = {r4[0], r4[1]}, b1[2] = {r4[2], r4[3]};

            mma_f16(zacc[0], ah, b0);
            mma_f16(zacc[1], ah, b1);
        }
        __syncthreads();
    }

    // ---- output: add bias, scale by 1/norm ----
#pragma unroll
    for (int nt = 0; nt < 2; nt++)
#pragma unroll
        for (int hp = 0; hp < 2; hp++) {
            int p = (lane >> 2) + hp * 8;
            int i = bi * 4 + (p >> 2), j = bj * 4 + (p & 3);
            float invn = 1.f / g_norm[i * R_DIM + j];
            int z0 = wz0 + nt * 8 + (lane & 3) * 2;
            float2 o;
            o.x = (zacc[nt][hp * 2 + 0] + __ldg(b_out + z0)) * invn;
            o.y = (zacc[nt][hp * 2 + 1] + __ldg(b_out + z0 + 1)) * invn;
            *(float2*)(out + ((size_t)i * R_DIM + j) * CZ + z0) = o;
        }
}

// ---------------------------------------------------------------------------
extern "C" void kernel_launch(void* const* d_in, const int* in_sizes, int n_in,
                              void* d_out, int out_size)
{
    const float* m_1    = (const float*)d_in[0];
    const float* m_2    = (const float*)d_in[1];
    const float* mask_1 = (const float*)d_in[2];
    const float* mask_2 = (const float*)d_in[3];
    const float* ln1_w  = (const float*)d_in[4];
    const float* ln1_b  = (const float*)d_in[5];
    const float* ln2_w  = (const float*)d_in[6];
    const float* ln2_b  = (const float*)d_in[7];
    const float* w1     = (const float*)d_in[8];
    const float* b1     = (const float*)d_in[9];
    const float* w2     = (const float*)d_in[10];
    const float* b2     = (const float*)d_in[11];
    const float* w_out  = (const float*)d_in[12];
    const float* b_out  = (const float*)d_in[13];
    float* out = (float*)d_out;

    cudaFuncSetAttribute(fused_kernel,
                         cudaFuncAttributeMaxDynamicSharedMemorySize, 65536);

    lnproj_kernel<<<(S_DIM * R_DIM) / 8, 256>>>(m_1, mask_1, ln1_w, ln1_b, w1, b1, 0);
    lnproj_kernel<<<(S_DIM * R_DIM) / 8, 256>>>(m_2, mask_2, ln2_w, ln2_b, w2, b2, 1);
    prep_kernel<<<R_DIM, 256>>>(mask_1, mask_2, w_out);
    fused_kernel<<<dim3(64, 64), 256, 65536>>>(b_out, out);
}

// round 8
// speedup vs baseline: 10.6918x; 1.1025x over previous
#include <cuda_runtime.h>
#include <cuda_bf16.h>
#include <cuda_fp16.h>
#include <cstdint>

#define S_DIM 128
#define R_DIM 256
#define CM    256
#define H_DIM 32
#define CZ    128
#define LN_EPS 1e-5f
#define EPS_N  1e-3f

// GEMM1 operands: [8192, 128] fp16, row-major (m=(i*32+c), k=s)
__device__ __half gAf[8192 * 128];
__device__ __half gBf[8192 * 128];
// Projection weight: w_out transposed, fp16: [128 z][1024 k]
__device__ __half gWf[128 * 1024];
__device__ float g_norm[R_DIM * R_DIM];

// ---------------------------------------------------------------------------
// helpers
// ---------------------------------------------------------------------------
__device__ __forceinline__ uint32_t smem_u32(const void* p) {
    uint32_t a;
    asm("{ .reg .u64 t; cvta.to.shared.u64 t, %1; cvt.u32.u64 %0, t; }" : "=r"(a) : "l"(p));
    return a;
}
#define SWZ128(o) ((o) ^ (((o) >> 3) & 0x70))
#define CP_ASYNC16(dst, src) asm volatile("cp.async.cg.shared.global [%0], [%1], 16;" :: "r"(dst), "l"(src))
#define CP_COMMIT()          asm volatile("cp.async.commit_group;" ::: "memory")
#define CP_WAIT(n)           asm volatile("cp.async.wait_group %0;" :: "n"(n) : "memory")

__device__ __forceinline__ void ldsm_x4(uint32_t* r, uint32_t addr) {
    asm volatile("ldmatrix.sync.aligned.m8n8.x4.shared.b16 {%0,%1,%2,%3}, [%4];"
                 : "=r"(r[0]), "=r"(r[1]), "=r"(r[2]), "=r"(r[3]) : "r"(addr));
}
__device__ __forceinline__ void mma_f16(float* d, const uint32_t* a, const uint32_t* b) {
    asm volatile(
        "mma.sync.aligned.m16n8k16.row.col.f32.f16.f16.f32 "
        "{%0,%1,%2,%3}, {%4,%5,%6,%7}, {%8,%9}, {%0,%1,%2,%3};"
        : "+f"(d[0]), "+f"(d[1]), "+f"(d[2]), "+f"(d[3])
        : "r"(a[0]), "r"(a[1]), "r"(a[2]), "r"(a[3]),
          "r"(b[0]), "r"(b[1]));
}

// ---------------------------------------------------------------------------
// Prologue: one kernel, block-dispatched.
//   blocks [0,4096):    LN+proj input 1 -> gAf
//   blocks [4096,8192): LN+proj input 2 -> gBf
//   blocks [8192,8448): norm matrix row + w_out transpose
// ---------------------------------------------------------------------------
__global__ void __launch_bounds__(256) prologue_kernel(
    const float* __restrict__ m1, const float* __restrict__ mask1,
    const float* __restrict__ ln1w, const float* __restrict__ ln1b,
    const float* __restrict__ w1, const float* __restrict__ b1,
    const float* __restrict__ m2, const float* __restrict__ mask2,
    const float* __restrict__ ln2w, const float* __restrict__ ln2b,
    const float* __restrict__ w2, const float* __restrict__ b2,
    const float* __restrict__ w_out)
{
    const int blk = blockIdx.x;
    if (blk < 8192) {
        const int which = blk >> 12;                // 0 or 1
        const float* m    = which ? m2 : m1;
        const float* mask = which ? mask2 : mask1;
        const float* lnw  = which ? ln2w : ln1w;
        const float* lnb  = which ? ln2b : ln1b;
        const float* w    = which ? w2 : w1;
        const float* bias = which ? b2 : b1;

        __shared__ float xs[8][CM];
        const int warp = threadIdx.x >> 5, lane = threadIdx.x & 31;
        const int q = (blk & 4095) * 8 + warp;      // row in [0, S*R)
        const int s = q >> 8, i = q & 255;

        const float* row = m + (size_t)q * CM;
        float x[8], sum = 0.f;
#pragma unroll
        for (int k = 0; k < 8; k++) { x[k] = row[lane + 32 * k]; sum += x[k]; }
#pragma unroll
        for (int o = 16; o; o >>= 1) sum += __shfl_xor_sync(0xffffffffu, sum, o);
        const float mu = sum * (1.f / CM);
        float vs = 0.f;
#pragma unroll
        for (int k = 0; k < 8; k++) { float d = x[k] - mu; vs += d * d; }
#pragma unroll
        for (int o = 16; o; o >>= 1) vs += __shfl_xor_sync(0xffffffffu, vs, o);
        const float rstd = rsqrtf(vs * (1.f / CM) + LN_EPS);
#pragma unroll
        for (int k = 0; k < 8; k++) {
            int c = lane + 32 * k;
            xs[warp][c] = (x[k] - mu) * rstd * lnw[c] + lnb[c];
        }
        __syncwarp();

        const float mk = mask[q];
        const int h = lane;
        float a0 = 0.f, a1 = 0.f, a2 = 0.f, a3 = 0.f;
#pragma unroll 4
        for (int c = 0; c < CM; c += 4) {
            a0 += xs[warp][c + 0] * w[(c + 0) * H_DIM + h];
            a1 += xs[warp][c + 1] * w[(c + 1) * H_DIM + h];
            a2 += xs[warp][c + 2] * w[(c + 2) * H_DIM + h];
            a3 += xs[warp][c + 3] * w[(c + 3) * H_DIM + h];
        }
        float acc = (bias[h] + ((a0 + a1) + (a2 + a3))) * mk;

        size_t dst = ((size_t)i * 32 + h) * 128 + s;
        if (which == 0) gAf[dst] = __float2half_rn(acc);
        else            gBf[dst] = __float2half_rn(acc);
    } else {
        const int i = blk - 8192, j = threadIdx.x;
        float sum = 0.f;
#pragma unroll 4
        for (int s = 0; s < S_DIM; s++)
            sum += mask1[s * R_DIM + i] * mask2[s * R_DIM + j];
        g_norm[i * R_DIM + j] = sum + EPS_N;

        int idx = i * 256 + j;
#pragma unroll
        for (int r = 0; r < 2; r++) {
            int id = idx + r * 65536;
            int k = id >> 7, n = id & 127;
            gWf[n * 1024 + k] = __float2half_rn(w_out[k * CZ + n]);
        }
    }
}

// ---------------------------------------------------------------------------
// Mainloop blocks (fp16). K-chunk = 64 elems, SW128 tiles.
// Chunk buffer: A[128][64] (16 KB) | B[128][64] (16 KB) = 32 KB.
// ---------------------------------------------------------------------------
__device__ __forceinline__ void load_chunk_async(
    uint32_t sbuf, int m0, int n0, int k0, int t)
{
#pragma unroll
    for (int it = 0; it < 8; it++) {
        int id = it * 256 + t;           // 2048 16B-chunks
        int tile = id >> 10;
        int rem = id & 1023;
        int r = rem >> 3;
        int c8 = (rem & 7) * 8;
        const __half* src = (tile == 0)
            ? gAf + (size_t)(m0 + r) * 128 + k0 + c8
            : gBf + (size_t)(n0 + r) * 128 + k0 + c8;
        uint32_t off = (uint32_t)(r * 128 + c8 * 2);
        CP_ASYNC16(sbuf + tile * 16384 + SWZ128(off), src);
    }
}

__device__ __forceinline__ void compute_chunk(
    uint32_t sbuf, int wm0, int wn0, int lane, float (*acc)[4][4])
{
    const int quad = lane >> 3, r8 = lane & 7;
#pragma unroll
    for (int ks = 0; ks < 4; ks++) {
        const int kb = ks * 32;
        uint32_t a4[4][4];
#pragma unroll
        for (int mf = 0; mf < 4; mf++) {
            int row = wm0 + mf * 16 + (quad & 1) * 8 + r8;
            int kbyte = kb + (quad >> 1) * 16;
            ldsm_x4(a4[mf], sbuf + SWZ128((uint32_t)(row * 128 + kbyte)));
        }
        uint32_t b4[4][2];
#pragma unroll
        for (int nb = 0; nb < 2; nb++) {
            int row = wn0 + nb * 16 + (quad >> 1) * 8 + r8;
            int kbyte = kb + (quad & 1) * 16;
            uint32_t r4[4];
            ldsm_x4(r4, sbuf + 16384 + SWZ128((uint32_t)(row * 128 + kbyte)));
            b4[nb * 2][0] = r4[0]; b4[nb * 2][1] = r4[1];
            b4[nb * 2 + 1][0] = r4[2]; b4[nb * 2 + 1][1] = r4[3];
        }
#pragma unroll
        for (int mf = 0; mf < 4; mf++)
#pragma unroll
            for (int nf = 0; nf < 4; nf++)
                mma_f16(acc[mf][nf], a4[mf], b4[nf]);
    }
}

// ---------------------------------------------------------------------------
// Fused kernel. Smem (65536 B):
//   mainloop: chunk0 @0 (32 KB), chunk1 @32768 (32 KB)  [loaded up-front]
//   epilogue: O fp16 [16][1024] @0 (32 KB), W buf0 @32768, W buf1 @49152
// Epilogue compute: warps 0-3 only, each n=32 z-cols over full K.
// ---------------------------------------------------------------------------
__global__ void __launch_bounds__(256, 2) fused_kernel(
    const float* __restrict__ b_out, float* __restrict__ out)
{
    extern __shared__ char dsm[];
    const int t = threadIdx.x, wid = t >> 5, lane = t & 31;
    const int bi = blockIdx.y, bj = blockIdx.x;
    const int m0 = bi * 128, n0 = bj * 128;
    const int wm0 = (wid >> 2) * 64, wn0 = (wid & 3) * 32;
    const int quad = lane >> 3, r8 = lane & 7;
    uint32_t sb = smem_u32(dsm);

    float acc[4][4][4];
#pragma unroll
    for (int a = 0; a < 4; a++)
#pragma unroll
        for (int b = 0; b < 4; b++)
#pragma unroll
            for (int c = 0; c < 4; c++) acc[a][b][c] = 0.f;

    // ---- mainloop: both K-chunks loaded up-front, computed back-to-back ----
    load_chunk_async(sb, m0, n0, 0, t);
    load_chunk_async(sb + 32768, m0, n0, 64, t);
    CP_COMMIT();
    CP_WAIT(0);
    __syncthreads();
    compute_chunk(sb, wm0, wn0, lane, acc);
    compute_chunk(sb + 32768, wm0, wn0, lane, acc);
    __syncthreads();   // all reads done before O/W overwrite smem

    // ---- stage outer tile to smem fp16: [p=16][k=1024] ----
    // addr(p, kbyte) = p*2048 + (kbyte ^ ((p&7)<<4))
#pragma unroll
    for (int mf = 0; mf < 4; mf++)
#pragma unroll
        for (int nf = 0; nf < 4; nf++)
#pragma unroll
            for (int half = 0; half < 2; half++) {
                int gm = wm0 + mf * 16 + (lane >> 2) + half * 8;
                int gn = wn0 + nf * 8 + (lane & 3) * 2;
                int p = ((gm >> 5) << 2) | (gn >> 5);
                int k = ((gm & 31) << 5) | (gn & 31);
                __half2 hp;
                hp.x = __float2half_rn(acc[mf][nf][half * 2 + 0]);
                hp.y = __float2half_rn(acc[mf][nf][half * 2 + 1]);
                uint32_t off = (uint32_t)(p * 2048 + ((k * 2) ^ ((p & 7) << 4)));
                *(__half2*)(dsm + off) = hp;
            }

    // W chunk loader: [128 z rows][64 k] fp16 = 16 KB tile
    auto loadW = [&](int kc, int buf) {
#pragma unroll
        for (int it = 0; it < 4; it++) {
            int id = it * 256 + t;           // 1024 16B-chunks
            int r = id >> 3, c8 = (id & 7) * 8;
            const __half* src = gWf + (size_t)r * 1024 + kc * 64 + c8;
            uint32_t off = SWZ128((uint32_t)(r * 128 + c8 * 2));
            CP_ASYNC16(sb + 32768 + buf * 16384 + off, src);
        }
    };
    loadW(0, 0); CP_COMMIT();
    loadW(1, 1); CP_COMMIT();
    __syncthreads();   // O staged & visible

    // ---- projection: warps 0-3, each z[16][32] = O[16][1024]·W[32,1024]^T ----
    float zacc[4][4];
#pragma unroll
    for (int a = 0; a < 4; a++)
#pragma unroll
        for (int b = 0; b < 4; b++) zacc[a][b] = 0.f;
    const int wz0 = wid * 32;   // valid for wid<4

    for (int kc = 0; kc < 16; kc++) {
        if (kc < 15) CP_WAIT(1); else CP_WAIT(0);
        __syncthreads();
        if (wid < 4) {
            uint32_t wbase = sb + 32768 + (kc & 1) * 16384;
#pragma unroll
            for (int ks = 0; ks < 4; ks++) {
                int arow = (quad & 1) * 8 + r8;
                uint32_t akb = (uint32_t)(kc * 128 + ks * 32 + (quad >> 1) * 16);
                uint32_t aoff = (uint32_t)(arow * 2048) + (akb ^ ((uint32_t)(arow & 7) << 4));
                uint32_t ah[4];
                ldsm_x4(ah, sb + aoff);
#pragma unroll
                for (int nb = 0; nb < 2; nb++) {
                    int brow = wz0 + nb * 16 + (quad >> 1) * 8 + r8;
                    uint32_t bkb = (uint32_t)(ks * 32 + (quad & 1) * 16);
                    uint32_t r4[4];
                    ldsm_x4(r4, wbase + SWZ128((uint32_t)(brow * 128) + bkb));
                    uint32_t b0[2] = {r4[0], r4[1]}, b1[2] = {r4[2], r4[3]};
                    mma_f16(zacc[nb * 2], ah, b0);
                    mma_f16(zacc[nb * 2 + 1], ah, b1);
                }
            }
        }
        __syncthreads();
        if (kc + 2 < 16) { loadW(kc + 2, kc & 1); CP_COMMIT(); }
    }

    // ---- output: add bias, scale by 1/norm (warps 0-3) ----
    if (wid < 4) {
#pragma unroll
        for (int nt = 0; nt < 4; nt++)
#pragma unroll
            for (int hp = 0; hp < 2; hp++) {
                int p = (lane >> 2) + hp * 8;
                int i = bi * 4 + (p >> 2), j = bj * 4 + (p & 3);
                float invn = 1.f / g_norm[i * R_DIM + j];
                int z0 = wz0 + nt * 8 + (lane & 3) * 2;
                float2 o;
                o.x = (zacc[nt][hp * 2 + 0] + __ldg(b_out + z0)) * invn;
                o.y = (zacc[nt][hp * 2 + 1] + __ldg(b_out + z0 + 1)) * invn;
                *(float2*)(out + ((size_t)i * R_DIM + j) * CZ + z0) = o;
            }
    }
}

// ---------------------------------------------------------------------------
extern "C" void kernel_launch(void* const* d_in, const int* in_sizes, int n_in,
                              void* d_out, int out_size)
{
    const float* m_1    = (const float*)d_in[0];
    const float* m_2    = (const float*)d_in[1];
    const float* mask_1 = (const float*)d_in[2];
    const float* mask_2 = (const float*)d_in[3];
    const float* ln1_w  = (const float*)d_in[4];
    const float* ln1_b  = (const float*)d_in[5];
    const float* ln2_w  = (const float*)d_in[6];
    const float* ln2_b  = (const float*)d_in[7];
    const float* w1     = (const float*)d_in[8];
    const float* b1     = (const float*)d_in[9];
    const float* w2     = (const float*)d_in[10];
    const float* b2     = (const float*)d_in[11];
    const float* w_out  = (const float*)d_in[12];
    const float* b_out  = (const float*)d_in[13];
    float* out = (float*)d_out;

    cudaFuncSetAttribute(fused_kernel,
                         cudaFuncAttributeMaxDynamicSharedMemorySize, 65536);

    prologue_kernel<<<8448, 256>>>(m_1, mask_1, ln1_w, ln1_b, w1, b1,
                                   m_2, mask_2, ln2_w, ln2_b, w2, b2, w_out);
    fused_kernel<<<dim3(64, 64), 256, 65536>>>(b_out, out);
}

// round 10
// speedup vs baseline: 11.2315x; 1.0505x over previous
#include <cuda_runtime.h>
#include <cuda_bf16.h>
#include <cuda_fp16.h>
#include <cstdint>

#define S_DIM 128
#define R_DIM 256
#define CM    256
#define H_DIM 32
#define CZ    128
#define LN_EPS 1e-5f
#define EPS_N  1e-3f

// GEMM1 operands: [8192, 128] fp16, row-major (m=(i*32+c), k=s)
__device__ __half gAf[8192 * 128];
__device__ __half gBf[8192 * 128];
// Projection weight: w_out transposed, fp16: [128 z][1024 k]
__device__ __half gWf[128 * 1024];
__device__ float g_norm[R_DIM * R_DIM];

// ---------------------------------------------------------------------------
// helpers
// ---------------------------------------------------------------------------
__device__ __forceinline__ uint32_t smem_u32(const void* p) {
    uint32_t a;
    asm("{ .reg .u64 t; cvta.to.shared.u64 t, %1; cvt.u32.u64 %0, t; }" : "=r"(a) : "l"(p));
    return a;
}
#define SWZ128(o) ((o) ^ (((o) >> 3) & 0x70))
#define CP_ASYNC16(dst, src) asm volatile("cp.async.cg.shared.global [%0], [%1], 16;" :: "r"(dst), "l"(src))
#define CP_COMMIT()          asm volatile("cp.async.commit_group;" ::: "memory")
#define CP_WAIT(n)           asm volatile("cp.async.wait_group %0;" :: "n"(n) : "memory")

__device__ __forceinline__ void ldsm_x4(uint32_t* r, uint32_t addr) {
    asm volatile("ldmatrix.sync.aligned.m8n8.x4.shared.b16 {%0,%1,%2,%3}, [%4];"
                 : "=r"(r[0]), "=r"(r[1]), "=r"(r[2]), "=r"(r[3]) : "r"(addr));
}
__device__ __forceinline__ void mma_f16(float* d, const uint32_t* a, const uint32_t* b) {
    asm volatile(
        "mma.sync.aligned.m16n8k16.row.col.f32.f16.f16.f32 "
        "{%0,%1,%2,%3}, {%4,%5,%6,%7}, {%8,%9}, {%0,%1,%2,%3};"
        : "+f"(d[0]), "+f"(d[1]), "+f"(d[2]), "+f"(d[3])
        : "r"(a[0]), "r"(a[1]), "r"(a[2]), "r"(a[3]),
          "r"(b[0]), "r"(b[1]));
}

// ---------------------------------------------------------------------------
// Prologue: one kernel, block-dispatched.
//   blocks [0,8192): LN+proj. blk -> (which, i, sblk); warp w handles
//                    row (s = sblk*8+w, i). Transposed 16B stores.
//   blocks [8192,8448): norm matrix row + w_out transpose
// ---------------------------------------------------------------------------
__global__ void __launch_bounds__(256) prologue_kernel(
    const float* __restrict__ m1, const float* __restrict__ mask1,
    const float* __restrict__ ln1w, const float* __restrict__ ln1b,
    const float* __restrict__ w1, const float* __restrict__ b1,
    const float* __restrict__ m2, const float* __restrict__ mask2,
    const float* __restrict__ ln2w, const float* __restrict__ ln2b,
    const float* __restrict__ w2, const float* __restrict__ b2,
    const float* __restrict__ w_out)
{
    const int blk = blockIdx.x;
    if (blk < 8192) {
        const int which = blk >> 12;
        const int rem = blk & 4095;
        const int i = rem >> 4;
        const int sblk = rem & 15;

        const float* m    = which ? m2 : m1;
        const float* mask = which ? mask2 : mask1;
        const float* lnw  = which ? ln2w : ln1w;
        const float* lnb  = which ? ln2b : ln1b;
        const float* w    = which ? w2 : w1;
        const float* bias = which ? b2 : b1;

        __shared__ float xs[8][CM];
        __shared__ __half ts[32][8];
        const int warp = threadIdx.x >> 5, lane = threadIdx.x & 31;
        const int s = sblk * 8 + warp;
        const int q = s * 256 + i;

        const float* row = m + (size_t)q * CM;
        float x[8], sum = 0.f;
#pragma unroll
        for (int k = 0; k < 8; k++) { x[k] = row[lane + 32 * k]; sum += x[k]; }
#pragma unroll
        for (int o = 16; o; o >>= 1) sum += __shfl_xor_sync(0xffffffffu, sum, o);
        const float mu = sum * (1.f / CM);
        float vs = 0.f;
#pragma unroll
        for (int k = 0; k < 8; k++) { float d = x[k] - mu; vs += d * d; }
#pragma unroll
        for (int o = 16; o; o >>= 1) vs += __shfl_xor_sync(0xffffffffu, vs, o);
        const float rstd = rsqrtf(vs * (1.f / CM) + LN_EPS);
#pragma unroll
        for (int k = 0; k < 8; k++) {
            int c = lane + 32 * k;
            xs[warp][c] = (x[k] - mu) * rstd * lnw[c] + lnb[c];
        }
        __syncwarp();

        const float mk = mask[q];
        const int h = lane;
        float a0 = 0.f, a1 = 0.f, a2 = 0.f, a3 = 0.f;
#pragma unroll 4
        for (int c = 0; c < CM; c += 4) {
            a0 += xs[warp][c + 0] * w[(c + 0) * H_DIM + h];
            a1 += xs[warp][c + 1] * w[(c + 1) * H_DIM + h];
            a2 += xs[warp][c + 2] * w[(c + 2) * H_DIM + h];
            a3 += xs[warp][c + 3] * w[(c + 3) * H_DIM + h];
        }
        float acc = (bias[h] + ((a0 + a1) + (a2 + a3))) * mk;

        ts[h][warp] = __float2half_rn(acc);
        __syncthreads();

        if (threadIdx.x < 32) {
            int hh = threadIdx.x;
            uint4 v = *(uint4*)&ts[hh][0];
            __half* dst = (which == 0 ? gAf : gBf);
            *(uint4*)&dst[((size_t)i * 32 + hh) * 128 + sblk * 8] = v;
        }
    } else {
        const int i = blk - 8192, j = threadIdx.x;
        float sum = 0.f;
#pragma unroll 4
        for (int s = 0; s < S_DIM; s++)
            sum += mask1[s * R_DIM + i] * mask2[s * R_DIM + j];
        g_norm[i * R_DIM + j] = sum + EPS_N;

        int idx = i * 256 + j;
#pragma unroll
        for (int r = 0; r < 2; r++) {
            int id = idx + r * 65536;
            int k = id >> 7, n = id & 127;
            gWf[n * 1024 + k] = __float2half_rn(w_out[k * CZ + n]);
        }
    }
}

// ---------------------------------------------------------------------------
// Mainloop blocks (fp16). K-chunk = 64 elems, SW128 tiles.
// Chunk buffer: A[128][64] (16 KB) | B[128][64] (16 KB) = 32 KB.
// ---------------------------------------------------------------------------
__device__ __forceinline__ void load_chunk_async(
    uint32_t sbuf, int m0, int n0, int k0, int t)
{
#pragma unroll
    for (int it = 0; it < 8; it++) {
        int id = it * 256 + t;           // 2048 16B-chunks
        int tile = id >> 10;
        int rem = id & 1023;
        int r = rem >> 3;
        int c8 = (rem & 7) * 8;
        const __half* src = (tile == 0)
            ? gAf + (size_t)(m0 + r) * 128 + k0 + c8
            : gBf + (size_t)(n0 + r) * 128 + k0 + c8;
        uint32_t off = (uint32_t)(r * 128 + c8 * 2);
        CP_ASYNC16(sbuf + tile * 16384 + SWZ128(off), src);
    }
}

__device__ __forceinline__ void compute_chunk(
    uint32_t sbuf, int wm0, int wn0, int lane, float (*acc)[4][4])
{
    const int quad = lane >> 3, r8 = lane & 7;
#pragma unroll
    for (int ks = 0; ks < 4; ks++) {
        const int kb = ks * 32;
        uint32_t a4[4][4];
#pragma unroll
        for (int mf = 0; mf < 4; mf++) {
            int row = wm0 + mf * 16 + (quad & 1) * 8 + r8;
            int kbyte = kb + (quad >> 1) * 16;
            ldsm_x4(a4[mf], sbuf + SWZ128((uint32_t)(row * 128 + kbyte)));
        }
        uint32_t b4[4][2];
#pragma unroll
        for (int nb = 0; nb < 2; nb++) {
            int row = wn0 + nb * 16 + (quad >> 1) * 8 + r8;
            int kbyte = kb + (quad & 1) * 16;
            uint32_t r4[4];
            ldsm_x4(r4, sbuf + 16384 + SWZ128((uint32_t)(row * 128 + kbyte)));
            b4[nb * 2][0] = r4[0]; b4[nb * 2][1] = r4[1];
            b4[nb * 2 + 1][0] = r4[2]; b4[nb * 2 + 1][1] = r4[3];
        }
#pragma unroll
        for (int mf = 0; mf < 4; mf++)
#pragma unroll
            for (int nf = 0; nf < 4; nf++)
                mma_f16(acc[mf][nf], a4[mf], b4[nf]);
    }
}

// ---------------------------------------------------------------------------
// Fused kernel. Smem (98304 B = 96 KB):
//   mainloop: A0@0 B0@16K | A1@32K B1@48K (both K-chunks up-front)
//   epilogue: O fp16 [16][1024] @0 (32 KB), W buf0 @32K (32 KB), W buf1 @64K
// Epilogue: all 8 warps, each n=16 z-cols; W streamed in 8 chunks of 128 k.
// ---------------------------------------------------------------------------
__global__ void __launch_bounds__(256, 2) fused_kernel(
    const float* __restrict__ b_out, float* __restrict__ out)
{
    extern __shared__ char dsm[];
    const int t = threadIdx.x, wid = t >> 5, lane = t & 31;
    const int bi = blockIdx.y, bj = blockIdx.x;
    const int m0 = bi * 128, n0 = bj * 128;
    const int wm0 = (wid >> 2) * 64, wn0 = (wid & 3) * 32;
    const int quad = lane >> 3, r8 = lane & 7;
    uint32_t sb = smem_u32(dsm);

    float acc[4][4][4];
#pragma unroll
    for (int a = 0; a < 4; a++)
#pragma unroll
        for (int b = 0; b < 4; b++)
#pragma unroll
            for (int c = 0; c < 4; c++) acc[a][b][c] = 0.f;

    // ---- mainloop: both K-chunks loaded up-front, computed back-to-back ----
    load_chunk_async(sb, m0, n0, 0, t);
    load_chunk_async(sb + 32768, m0, n0, 64, t);
    CP_COMMIT();
    CP_WAIT(0);
    __syncthreads();
    compute_chunk(sb, wm0, wn0, lane, acc);
    compute_chunk(sb + 32768, wm0, wn0, lane, acc);
    __syncthreads();   // all reads done before O/W overwrite smem

    // W chunk loader: [128 z rows][128 k] fp16 = 32 KB (two 16 KB sub-tiles)
    auto loadW = [&](int kc, int buf) {
        uint32_t base = sb + 32768 + (uint32_t)buf * 32768;
#pragma unroll
        for (int it = 0; it < 8; it++) {
            int id = it * 256 + t;            // 2048 16B-chunks
            int r = id >> 4;                  // z row 0..127
            int c8 = (id & 15) * 8;           // k offset 0..120
            const __half* src = gWf + (size_t)r * 1024 + kc * 128 + c8;
            uint32_t off = (uint32_t)((c8 >> 6) * 16384)
                         + SWZ128((uint32_t)(r * 128 + (c8 & 63) * 2));
            CP_ASYNC16(base + off, src);
        }
    };
    loadW(0, 0); CP_COMMIT();
    loadW(1, 1); CP_COMMIT();

    // ---- stage outer tile to smem fp16: [p=16][k=1024] ----
    // addr(p, kbyte) = p*2048 + (kbyte ^ ((p&7)<<4))
#pragma unroll
    for (int mf = 0; mf < 4; mf++)
#pragma unroll
        for (int nf = 0; nf < 4; nf++)
#pragma unroll
            for (int half = 0; half < 2; half++) {
                int gm = wm0 + mf * 16 + (lane >> 2) + half * 8;
                int gn = wn0 + nf * 8 + (lane & 3) * 2;
                int p = ((gm >> 5) << 2) | (gn >> 5);
                int k = ((gm & 31) << 5) | (gn & 31);
                __half2 hp;
                hp.x = __float2half_rn(acc[mf][nf][half * 2 + 0]);
                hp.y = __float2half_rn(acc[mf][nf][half * 2 + 1]);
                uint32_t off = (uint32_t)(p * 2048 + ((k * 2) ^ ((p & 7) << 4)));
                *(__half2*)(dsm + off) = hp;
            }

    // ---- projection: 8 warps, each z[16][16] per chunk; 8 chunks of 128 k ----
    float zacc[2][4] = {{0.f, 0.f, 0.f, 0.f}, {0.f, 0.f, 0.f, 0.f}};
    const int wz0 = wid * 16;

    for (int kc = 0; kc < 8; kc++) {
        if (kc < 7) CP_WAIT(1); else CP_WAIT(0);
        __syncthreads();   // W chunk kc + (kc==0: O staging) visible to all
        uint32_t wb = sb + 32768 + (uint32_t)(kc & 1) * 32768;
#pragma unroll
        for (int ks = 0; ks < 8; ks++) {
            int arow = (quad & 1) * 8 + r8;
            uint32_t akb = (uint32_t)(kc * 256 + ks * 32 + (quad >> 1) * 16);
            uint32_t aoff = (uint32_t)(arow * 2048) + (akb ^ ((uint32_t)(arow & 7) << 4));
            uint32_t ah[4];
            ldsm_x4(ah, sb + aoff);

            int brow = wz0 + (quad >> 1) * 8 + r8;
            uint32_t inner = (uint32_t)((ks & 3) * 32 + (quad & 1) * 16);
            uint32_t boff = (uint32_t)((ks >> 2) * 16384)
                          + SWZ128((uint32_t)(brow * 128) + inner);
            uint32_t r4[4];
            ldsm_x4(r4, wb + boff);
            uint32_t b0[2] = {r4[0], r4[1]}, b1[2] = {r4[2], r4[3]};
            mma_f16(zacc[0], ah, b0);
            mma_f16(zacc[1], ah, b1);
        }
        __syncthreads();   // chunk kc fully consumed before overwrite
        if (kc + 2 < 8) { loadW(kc + 2, kc & 1); CP_COMMIT(); }
    }

    // ---- output: add bias, scale by 1/norm ----
#pragma unroll
    for (int nt = 0; nt < 2; nt++)
#pragma unroll
        for (int hp = 0; hp < 2; hp++) {
            int p = (lane >> 2) + hp * 8;
            int i = bi * 4 + (p >> 2), j = bj * 4 + (p & 3);
            float invn = 1.f / g_norm[i * R_DIM + j];
            int z0 = wz0 + nt * 8 + (lane & 3) * 2;
            float2 o;
            o.x = (zacc[nt][hp * 2 + 0] + __ldg(b_out + z0)) * invn;
            o.y = (zacc[nt][hp * 2 + 1] + __ldg(b_out + z0 + 1)) * invn;
            *(float2*)(out + ((size_t)i * R_DIM + j) * CZ + z0) = o;
        }
}

// ---------------------------------------------------------------------------
extern "C" void kernel_launch(void* const* d_in, const int* in_sizes, int n_in,
                              void* d_out, int out_size)
{
    const float* m_1    = (const float*)d_in[0];
    const float* m_2    = (const float*)d_in[1];
    const float* mask_1 = (const float*)d_in[2];
    const float* mask_2 = (const float*)d_in[3];
    const float* ln1_w  = (const float*)d_in[4];
    const float* ln1_b  = (const float*)d_in[5];
    const float* ln2_w  = (const float*)d_in[6];
    const float* ln2_b  = (const float*)d_in[7];
    const float* w1     = (const float*)d_in[8];
    const float* b1     = (const float*)d_in[9];
    const float* w2     = (const float*)d_in[10];
    const float* b2     = (const float*)d_in[11];
    const float* w_out  = (const float*)d_in[12];
    const float* b_out  = (const float*)d_in[13];
    float* out = (float*)d_out;

    cudaFuncSetAttribute(fused_kernel,
                         cudaFuncAttributeMaxDynamicSharedMemorySize, 98304);

    prologue_kernel<<<8448, 256>>>(m_1, mask_1, ln1_w, ln1_b, w1, b1,
                                   m_2, mask_2, ln2_w, ln2_b, w2, b2, w_out);
    fused_kernel<<<dim3(64, 64), 256, 98304>>>(b_out, out);
}

// round 11
// speedup vs baseline: 14.8667x; 1.3237x over previous
#include <cuda_runtime.h>
#include <cuda_bf16.h>
#include <cuda_fp16.h>
#include <cstdint>

#define S_DIM 128
#define R_DIM 256
#define CM    256
#define H_DIM 32
#define CZ    128
#define LN_EPS 1e-5f
#define EPS_N  1e-3f

// GEMM1 operands: [8192, 128] fp16, row-major (m=(i*32+h), k=s)
__device__ __half gAf[8192 * 128];
__device__ __half gBf[8192 * 128];
// w_out in mma-B-fragment order:
// u = (((ktg*8 + ntp)*32 + lane)*4 + r2), r2 = ntsub*2 + rr
//   k = ktg*16 + (lane&3)*2 + rr*8 ; n = (ntp*2+ntsub)*8 + (lane>>2)
//   value = pack_f16(w_out[k][n], w_out[k+1][n])
__device__ uint32_t gWfrag[131072];
__device__ float g_norm[R_DIM * R_DIM];

// ---------------------------------------------------------------------------
__device__ __forceinline__ uint32_t smem_u32(const void* p) {
    uint32_t a;
    asm("{ .reg .u64 t; cvta.to.shared.u64 t, %1; cvt.u32.u64 %0, t; }" : "=r"(a) : "l"(p));
    return a;
}
#define SWZ128(o) ((o) ^ (((o) >> 3) & 0x70))
#define CP_ASYNC16(dst, src) asm volatile("cp.async.cg.shared.global [%0], [%1], 16;" :: "r"(dst), "l"(src))
#define CP_COMMIT()          asm volatile("cp.async.commit_group;" ::: "memory")
#define CP_WAIT(n)           asm volatile("cp.async.wait_group %0;" :: "n"(n) : "memory")

__device__ __forceinline__ void ldsm_x4(uint32_t* r, uint32_t addr) {
    asm volatile("ldmatrix.sync.aligned.m8n8.x4.shared.b16 {%0,%1,%2,%3}, [%4];"
                 : "=r"(r[0]), "=r"(r[1]), "=r"(r[2]), "=r"(r[3]) : "r"(addr));
}
__device__ __forceinline__ void mma_f16(float* d, const uint32_t* a, const uint32_t* b) {
    asm volatile(
        "mma.sync.aligned.m16n8k16.row.col.f32.f16.f16.f32 "
        "{%0,%1,%2,%3}, {%4,%5,%6,%7}, {%8,%9}, {%0,%1,%2,%3};"
        : "+f"(d[0]), "+f"(d[1]), "+f"(d[2]), "+f"(d[3])
        : "r"(a[0]), "r"(a[1]), "r"(a[2]), "r"(a[3]),
          "r"(b[0]), "r"(b[1]));
}

// ---------------------------------------------------------------------------
// Prologue. Dynamic smem 69120 B:
//   region0 @0     : wr [256][33] fp32 (33792 B), later reused as xs [32][256] fp32
//   region1 @33792 : wt [32 h][64 c4] fp32, 16B groups swizzled by (c4 ^ (h&7))
//   region2 @66560 : ts [32 h][40] fp16 (2560 B) transpose-out staging
// blocks [0,2048): LN+proj, blk -> (which=blk>>10, i=(blk&1023)>>2, sgrp=blk&3)
//   warp w handles rows s = sgrp*32 + w*4 .. +3
// blocks [2048,2304): norm row + gWfrag fill
// ---------------------------------------------------------------------------
__global__ void __launch_bounds__(256) prologue_kernel(
    const float* __restrict__ m1, const float* __restrict__ mask1,
    const float* __restrict__ ln1w, const float* __restrict__ ln1b,
    const float* __restrict__ w1, const float* __restrict__ b1,
    const float* __restrict__ m2, const float* __restrict__ mask2,
    const float* __restrict__ ln2w, const float* __restrict__ ln2b,
    const float* __restrict__ w2, const float* __restrict__ b2,
    const float* __restrict__ w_out)
{
    extern __shared__ char psm[];
    const int blk = blockIdx.x;
    const int t = threadIdx.x;

    if (blk < 2048) {
        const int which = blk >> 10;
        const int rem = blk & 1023;
        const int i = rem >> 2;
        const int sgrp = rem & 3;

        const float* m    = which ? m2 : m1;
        const float* mask = which ? mask2 : mask1;
        const float* lnw  = which ? ln2w : ln1w;
        const float* lnb  = which ? ln2b : ln1b;
        const float* w    = which ? w2 : w1;
        const float* bias = which ? b2 : b1;

        float* wr = (float*)psm;                    // [256][33]
        float* xs = (float*)psm;                    // [32][256] (aliases wr later)
        float* wt = (float*)(psm + 33792);          // [32][64 c4] swizzled
        __half* ts = (__half*)(psm + 66560);        // [32][40]

        const int warp = t >> 5, lane = t & 31;

        // phase 1: load w coalesced into padded wr
#pragma unroll
        for (int k = 0; k < 32; k++) {
            int id = t + k * 256;
            int c = id >> 5, h = id & 31;
            wr[c * 33 + h] = w[c * 32 + h];
        }
        __syncthreads();

        // phase 2: build swizzled wt[h][c]
        {
            int h = t >> 3;
#pragma unroll
            for (int k = 0; k < 8; k++) {
                int c4 = (t & 7) + k * 8;
                float4 v;
                v.x = wr[(c4 * 4 + 0) * 33 + h];
                v.y = wr[(c4 * 4 + 1) * 33 + h];
                v.z = wr[(c4 * 4 + 2) * 33 + h];
                v.w = wr[(c4 * 4 + 3) * 33 + h];
                *(float4*)((char*)wt + h * 1024 + ((c4 ^ (h & 7)) << 4)) = v;
            }
        }
        __syncthreads();   // wr fully consumed -> region reusable as xs

        // phase 3: LN 4 rows per warp -> xs
        const int c0 = lane * 8;
        float4 lw0 = *(const float4*)(lnw + c0);
        float4 lw1 = *(const float4*)(lnw + c0 + 4);
        float4 lb0 = *(const float4*)(lnb + c0);
        float4 lb1 = *(const float4*)(lnb + c0 + 4);
#pragma unroll
        for (int rr = 0; rr < 4; rr++) {
            int s = sgrp * 32 + warp * 4 + rr;
            const float* row = m + ((size_t)s * 256 + i) * CM;
            float4 v0 = *(const float4*)(row + c0);
            float4 v1 = *(const float4*)(row + c0 + 4);
            float sum = v0.x + v0.y + v0.z + v0.w + v1.x + v1.y + v1.z + v1.w;
#pragma unroll
            for (int o = 16; o; o >>= 1) sum += __shfl_xor_sync(0xffffffffu, sum, o);
            float mu = sum * (1.f / CM);
            float vs = (v0.x-mu)*(v0.x-mu) + (v0.y-mu)*(v0.y-mu) + (v0.z-mu)*(v0.z-mu)
                     + (v0.w-mu)*(v0.w-mu) + (v1.x-mu)*(v1.x-mu) + (v1.y-mu)*(v1.y-mu)
                     + (v1.z-mu)*(v1.z-mu) + (v1.w-mu)*(v1.w-mu);
#pragma unroll
            for (int o = 16; o; o >>= 1) vs += __shfl_xor_sync(0xffffffffu, vs, o);
            float rstd = rsqrtf(vs * (1.f / CM) + LN_EPS);
            float4 o0, o1;
            o0.x = (v0.x - mu) * rstd * lw0.x + lb0.x;
            o0.y = (v0.y - mu) * rstd * lw0.y + lb0.y;
            o0.z = (v0.z - mu) * rstd * lw0.z + lb0.z;
            o0.w = (v0.w - mu) * rstd * lw0.w + lb0.w;
            o1.x = (v1.x - mu) * rstd * lw1.x + lb1.x;
            o1.y = (v1.y - mu) * rstd * lw1.y + lb1.y;
            o1.z = (v1.z - mu) * rstd * lw1.z + lb1.z;
            o1.w = (v1.w - mu) * rstd * lw1.w + lb1.w;
            *(float4*)(xs + (warp * 4 + rr) * 256 + c0)     = o0;
            *(float4*)(xs + (warp * 4 + rr) * 256 + c0 + 4) = o1;
        }
        __syncthreads();

        // phase 4: dot. lane h, 4 rows per warp.
        {
            const int h = lane;
            float a0 = 0.f, a1 = 0.f, a2 = 0.f, a3 = 0.f;
            const float* xr0 = xs + (warp * 4 + 0) * 256;
            const float* xr1 = xs + (warp * 4 + 1) * 256;
            const float* xr2 = xs + (warp * 4 + 2) * 256;
            const float* xr3 = xs + (warp * 4 + 3) * 256;
#pragma unroll 8
            for (int c4 = 0; c4 < 64; c4++) {
                float4 wv = *(const float4*)((char*)wt + h * 1024 + ((c4 ^ (h & 7)) << 4));
                float4 x0 = *(const float4*)(xr0 + c4 * 4);
                float4 x1 = *(const float4*)(xr1 + c4 * 4);
                float4 x2 = *(const float4*)(xr2 + c4 * 4);
                float4 x3 = *(const float4*)(xr3 + c4 * 4);
                a0 += x0.x * wv.x + x0.y * wv.y + x0.z * wv.z + x0.w * wv.w;
                a1 += x1.x * wv.x + x1.y * wv.y + x1.z * wv.z + x1.w * wv.w;
                a2 += x2.x * wv.x + x2.y * wv.y + x2.z * wv.z + x2.w * wv.w;
                a3 += x3.x * wv.x + x3.y * wv.y + x3.z * wv.z + x3.w * wv.w;
            }
            float bh = bias[h];
            float accs[4] = {a0, a1, a2, a3};
#pragma unroll
            for (int rr = 0; rr < 4; rr++) {
                int s = sgrp * 32 + warp * 4 + rr;
                float mk = mask[s * 256 + i];
                ts[h * 40 + warp * 4 + rr] = __float2half_rn((accs[rr] + bh) * mk);
            }
        }
        __syncthreads();

        // phase 5: vectorized transposed stores
        if (t < 128) {
            int h = t >> 2, grp = t & 3;
            uint4 v = *(uint4*)((char*)ts + h * 80 + grp * 16);
            __half* dst = (which ? gBf : gAf);
            *(uint4*)&dst[((size_t)i * 32 + h) * 128 + sgrp * 32 + grp * 8] = v;
        }
    } else {
        // prep: norm row + gWfrag fill
        const int p = blk - 2048;
        const int i = p, j = t;
        float sum = 0.f;
#pragma unroll 4
        for (int s = 0; s < S_DIM; s++)
            sum += mask1[s * R_DIM + i] * mask2[s * R_DIM + j];
        g_norm[i * R_DIM + j] = sum + EPS_N;

        int idx = p * 256 + t;
#pragma unroll
        for (int r = 0; r < 2; r++) {
            int u = idx + r * 65536;
            int r2 = u & 3;
            int lane = (u >> 2) & 31;
            int ntp = (u >> 7) & 7;
            int ktg = u >> 10;
            int ntsub = r2 >> 1, rr = r2 & 1;
            int k = ktg * 16 + (lane & 3) * 2 + rr * 8;
            int n = (ntp * 2 + ntsub) * 8 + (lane >> 2);
            unsigned short lo = __half_as_ushort(__float2half_rn(w_out[k * CZ + n]));
            unsigned short hi = __half_as_ushort(__float2half_rn(w_out[(k + 1) * CZ + n]));
            gWfrag[u] = (uint32_t)lo | ((uint32_t)hi << 16);
        }
    }
}

// ---------------------------------------------------------------------------
// Mainloop blocks (fp16). K-chunk = 64 elems, SW128 tiles. 32 KB per chunk.
// ---------------------------------------------------------------------------
__device__ __forceinline__ void load_chunk_async(
    uint32_t sbuf, int m0, int n0, int k0, int t)
{
#pragma unroll
    for (int it = 0; it < 8; it++) {
        int id = it * 256 + t;
        int tile = id >> 10;
        int rem = id & 1023;
        int r = rem >> 3;
        int c8 = (rem & 7) * 8;
        const __half* src = (tile == 0)
            ? gAf + (size_t)(m0 + r) * 128 + k0 + c8
            : gBf + (size_t)(n0 + r) * 128 + k0 + c8;
        uint32_t off = (uint32_t)(r * 128 + c8 * 2);
        CP_ASYNC16(sbuf + tile * 16384 + SWZ128(off), src);
    }
}

__device__ __forceinline__ void compute_chunk(
    uint32_t sbuf, int wm0, int wn0, int lane, float (*acc)[4][4])
{
    const int quad = lane >> 3, r8 = lane & 7;
#pragma unroll
    for (int ks = 0; ks < 4; ks++) {
        const int kb = ks * 32;
        uint32_t a4[4][4];
#pragma unroll
        for (int mf = 0; mf < 4; mf++) {
            int row = wm0 + mf * 16 + (quad & 1) * 8 + r8;
            int kbyte = kb + (quad >> 1) * 16;
            ldsm_x4(a4[mf], sbuf + SWZ128((uint32_t)(row * 128 + kbyte)));
        }
        uint32_t b4[4][2];
#pragma unroll
        for (int nb = 0; nb < 2; nb++) {
            int row = wn0 + nb * 16 + (quad >> 1) * 8 + r8;
            int kbyte = kb + (quad & 1) * 16;
            uint32_t r4[4];
            ldsm_x4(r4, sbuf + 16384 + SWZ128((uint32_t)(row * 128 + kbyte)));
            b4[nb * 2][0] = r4[0]; b4[nb * 2][1] = r4[1];
            b4[nb * 2 + 1][0] = r4[2]; b4[nb * 2 + 1][1] = r4[3];
        }
#pragma unroll
        for (int mf = 0; mf < 4; mf++)
#pragma unroll
            for (int nf = 0; nf < 4; nf++)
                mma_f16(acc[mf][nf], a4[mf], b4[nf]);
    }
}

// ---------------------------------------------------------------------------
// Fused kernel. Dynamic smem 100352 B:
//   mainloop: chunk0 @0 (32 KB), chunk1 @32768 (32 KB)
//   epilogue: O fp16 [16 p][1024 k] @0 (32 KB, 2048 B rows, 16B-grp swizzle)
//             reduction slab @32768: [8 w][16 p][132 floats] (8448 B/warp)
// Projection: K-partitioned. Warp w owns k in [w*128,(w+1)*128); W fragments
// come straight from L2 via coalesced LDG.128 in gWfrag order; then cross-warp
// fp32 reduction, bias, 1/norm, store.
// ---------------------------------------------------------------------------
__global__ void __launch_bounds__(256, 2) fused_kernel(
    const float* __restrict__ b_out, float* __restrict__ out)
{
    extern __shared__ char dsm[];
    const int t = threadIdx.x, wid = t >> 5, lane = t & 31;
    const int bi = blockIdx.y, bj = blockIdx.x;
    const int m0 = bi * 128, n0 = bj * 128;
    const int wm0 = (wid >> 2) * 64, wn0 = (wid & 3) * 32;
    const int quad = lane >> 3, r8 = lane & 7;
    uint32_t sb = smem_u32(dsm);

    float acc[4][4][4];
#pragma unroll
    for (int a = 0; a < 4; a++)
#pragma unroll
        for (int b = 0; b < 4; b++)
#pragma unroll
            for (int c = 0; c < 4; c++) acc[a][b][c] = 0.f;

    // ---- mainloop ----
    load_chunk_async(sb, m0, n0, 0, t);
    load_chunk_async(sb + 32768, m0, n0, 64, t);
    CP_COMMIT();
    CP_WAIT(0);
    __syncthreads();
    compute_chunk(sb, wm0, wn0, lane, acc);
    compute_chunk(sb + 32768, wm0, wn0, lane, acc);
    __syncthreads();   // all reads done before O overwrites smem

    // ---- stage outer tile to smem fp16: [p=16][k=1024] ----
#pragma unroll
    for (int mf = 0; mf < 4; mf++)
#pragma unroll
        for (int nf = 0; nf < 4; nf++)
#pragma unroll
            for (int half = 0; half < 2; half++) {
                int gm = wm0 + mf * 16 + (lane >> 2) + half * 8;
                int gn = wn0 + nf * 8 + (lane & 3) * 2;
                int p = ((gm >> 5) << 2) | (gn >> 5);
                int k = ((gm & 31) << 5) | (gn & 31);
                __half2 hp;
                hp.x = __float2half_rn(acc[mf][nf][half * 2 + 0]);
                hp.y = __float2half_rn(acc[mf][nf][half * 2 + 1]);
                uint32_t off = (uint32_t)(p * 2048 + ((k * 2) ^ ((p & 7) << 4)));
                *(__half2*)(dsm + off) = hp;
            }
    __syncthreads();   // O staged & visible to all warps

    // ---- K-partitioned projection: warp wid owns k-chunk wid (128 k) ----
    float zacc[16][4];
#pragma unroll
    for (int a = 0; a < 16; a++)
#pragma unroll
        for (int b = 0; b < 4; b++) zacc[a][b] = 0.f;

#pragma unroll
    for (int kt = 0; kt < 8; kt++) {
        int arow = (quad & 1) * 8 + r8;
        uint32_t akb = (uint32_t)(wid * 256 + kt * 32 + (quad >> 1) * 16);
        uint32_t aoff = (uint32_t)(arow * 2048) + (akb ^ ((uint32_t)(arow & 7) << 4));
        uint32_t ah[4];
        ldsm_x4(ah, sb + aoff);
#pragma unroll
        for (int ntp = 0; ntp < 8; ntp++) {
            const uint4* wp = reinterpret_cast<const uint4*>(gWfrag)
                            + ((wid * 8 + kt) * 8 + ntp) * 32 + lane;
            uint4 bv = __ldg(wp);
            uint32_t b0[2] = {bv.x, bv.y}, b1[2] = {bv.z, bv.w};
            mma_f16(zacc[ntp * 2],     ah, b0);
            mma_f16(zacc[ntp * 2 + 1], ah, b1);
        }
    }

    // ---- store partials: red[w][p][132 floats] ----
    {
        char* red = dsm + 32768 + wid * 8448;
#pragma unroll
        for (int nf = 0; nf < 16; nf++)
#pragma unroll
            for (int hh = 0; hh < 2; hh++) {
                int p = (lane >> 2) + hh * 8;
                int z = nf * 8 + (lane & 3) * 2;
                float2 v;
                v.x = zacc[nf][hh * 2 + 0];
                v.y = zacc[nf][hh * 2 + 1];
                *(float2*)(red + p * 528 + z * 4) = v;
            }
    }
    __syncthreads();

    // ---- sum 8 partials, bias, 1/norm, store ----
#pragma unroll
    for (int g2 = 0; g2 < 2; g2++) {
        int cell = t + g2 * 256;          // 512 float4 cells
        int p = cell >> 5;
        int z = (cell & 31) * 4;
        float4 s = {0.f, 0.f, 0.f, 0.f};
#pragma unroll
        for (int w = 0; w < 8; w++) {
            float4 v = *(float4*)(dsm + 32768 + w * 8448 + p * 528 + z * 4);
            s.x += v.x; s.y += v.y; s.z += v.z; s.w += v.w;
        }
        int i = bi * 4 + (p >> 2), j = bj * 4 + (p & 3);
        float invn = 1.f / g_norm[i * R_DIM + j];
        float4 bo = __ldg((const float4*)(b_out + z));
        float4 o;
        o.x = (s.x + bo.x) * invn;
        o.y = (s.y + bo.y) * invn;
        o.z = (s.z + bo.z) * invn;
        o.w = (s.w + bo.w) * invn;
        *(float4*)(out + ((size_t)i * R_DIM + j) * CZ + z) = o;
    }
}

// ---------------------------------------------------------------------------
extern "C" void kernel_launch(void* const* d_in, const int* in_sizes, int n_in,
                              void* d_out, int out_size)
{
    const float* m_1    = (const float*)d_in[0];
    const float* m_2    = (const float*)d_in[1];
    const float* mask_1 = (const float*)d_in[2];
    const float* mask_2 = (const float*)d_in[3];
    const float* ln1_w  = (const float*)d_in[4];
    const float* ln1_b  = (const float*)d_in[5];
    const float* ln2_w  = (const float*)d_in[6];
    const float* ln2_b  = (const float*)d_in[7];
    const float* w1     = (const float*)d_in[8];
    const float* b1     = (const float*)d_in[9];
    const float* w2     = (const float*)d_in[10];
    const float* b2     = (const float*)d_in[11];
    const float* w_out  = (const float*)d_in[12];
    const float* b_out  = (const float*)d_in[13];
    float* out = (float*)d_out;

    cudaFuncSetAttribute(prologue_kernel,
                         cudaFuncAttributeMaxDynamicSharedMemorySize, 69120);
    cudaFuncSetAttribute(fused_kernel,
                         cudaFuncAttributeMaxDynamicSharedMemorySize, 100352);

    prologue_kernel<<<2304, 256, 69120>>>(m_1, mask_1, ln1_w, ln1_b, w1, b1,
                                          m_2, mask_2, ln2_w, ln2_b, w2, b2, w_out);
    fused_kernel<<<dim3(64, 64), 256, 100352>>>(b_out, out);
}

// round 13
// speedup vs baseline: 17.7041x; 1.1909x over previous
#include <cuda_runtime.h>
#include <cuda_bf16.h>
#include <cuda_fp16.h>
#include <cstdint>

#define S_DIM 128
#define R_DIM 256
#define CM    256
#define H_DIM 32
#define CZ    128
#define LN_EPS 1e-5f
#define EPS_N  1e-3f

// GEMM1 operands: [8192, 128] fp16, row-major (m=(i*32+h), k=s)
__device__ __half gAf[8192 * 128];
__device__ __half gBf[8192 * 128];
// w_out in mma-B-fragment order (see R11): 131072 uint32
__device__ uint32_t gWfrag[131072];
// w1/w2 in mma-B-fragment order: u = which*4096 + kt*256 + ntp*128 + lane*4 + r2
__device__ uint32_t gW12[8192];
__device__ float g_norm[R_DIM * R_DIM];

// ---------------------------------------------------------------------------
__device__ __forceinline__ uint32_t smem_u32(const void* p) {
    uint32_t a;
    asm("{ .reg .u64 t; cvta.to.shared.u64 t, %1; cvt.u32.u64 %0, t; }" : "=r"(a) : "l"(p));
    return a;
}
#define SWZ128(o) ((o) ^ (((o) >> 3) & 0x70))
#define CP_ASYNC16(dst, src) asm volatile("cp.async.cg.shared.global [%0], [%1], 16;" :: "r"(dst), "l"(src))
#define CP_COMMIT()          asm volatile("cp.async.commit_group;" ::: "memory")
#define CP_WAIT(n)           asm volatile("cp.async.wait_group %0;" :: "n"(n) : "memory")

__device__ __forceinline__ void ldsm_x4(uint32_t* r, uint32_t addr) {
    asm volatile("ldmatrix.sync.aligned.m8n8.x4.shared.b16 {%0,%1,%2,%3}, [%4];"
                 : "=r"(r[0]), "=r"(r[1]), "=r"(r[2]), "=r"(r[3]) : "r"(addr));
}
__device__ __forceinline__ void mma_f16(float* d, const uint32_t* a, const uint32_t* b) {
    asm volatile(
        "mma.sync.aligned.m16n8k16.row.col.f32.f16.f16.f32 "
        "{%0,%1,%2,%3}, {%4,%5,%6,%7}, {%8,%9}, {%0,%1,%2,%3};"
        : "+f"(d[0]), "+f"(d[1]), "+f"(d[2]), "+f"(d[3])
        : "r"(a[0]), "r"(a[1]), "r"(a[2]), "r"(a[3]),
          "r"(b[0]), "r"(b[1]));
}

// ---------------------------------------------------------------------------
// Prep kernel (runs FIRST): norm matrix + gWfrag + gW12 fragment packing.
// 256 blocks x 256 threads.
// ---------------------------------------------------------------------------
__global__ void __launch_bounds__(256) prep_kernel(
    const float* __restrict__ mask1, const float* __restrict__ mask2,
    const float* __restrict__ w1, const float* __restrict__ w2,
    const float* __restrict__ w_out)
{
    const int p = blockIdx.x;
    const int t = threadIdx.x;
    const int i = p, j = t;
    float sum = 0.f;
#pragma unroll 4
    for (int s = 0; s < S_DIM; s++)
        sum += mask1[s * R_DIM + i] * mask2[s * R_DIM + j];
    g_norm[i * R_DIM + j] = sum + EPS_N;

    int idx = p * 256 + t;
#pragma unroll
    for (int r = 0; r < 2; r++) {
        int u = idx + r * 65536;
        int r2 = u & 3;
        int lane = (u >> 2) & 31;
        int ntp = (u >> 7) & 7;
        int ktg = u >> 10;
        int ntsub = r2 >> 1, rr = r2 & 1;
        int k = ktg * 16 + (lane & 3) * 2 + rr * 8;
        int n = (ntp * 2 + ntsub) * 8 + (lane >> 2);
        unsigned short lo = __half_as_ushort(__float2half_rn(w_out[k * CZ + n]));
        unsigned short hi = __half_as_ushort(__float2half_rn(w_out[(k + 1) * CZ + n]));
        gWfrag[u] = (uint32_t)lo | ((uint32_t)hi << 16);
    }
    if (idx < 8192) {
        int u = idx;
        int which = u >> 12;
        int u2 = u & 4095;
        int r2 = u2 & 3;
        int lane = (u2 >> 2) & 31;
        int ntp = (u2 >> 7) & 1;
        int kt = u2 >> 8;
        int ntsub = r2 >> 1, rr = r2 & 1;
        int k = kt * 16 + (lane & 3) * 2 + rr * 8;
        int n = (ntp * 2 + ntsub) * 8 + (lane >> 2);
        const float* wsrc = which ? w2 : w1;
        unsigned short lo = __half_as_ushort(__float2half_rn(wsrc[k * H_DIM + n]));
        unsigned short hi = __half_as_ushort(__float2half_rn(wsrc[(k + 1) * H_DIM + n]));
        gW12[u] = (uint32_t)lo | ((uint32_t)hi << 16);
    }
}

// ---------------------------------------------------------------------------
// LN + tensor-core projection kernel (512 blocks): blk -> (which=blk>>8, i=blk&255)
//   8 warps, warp w owns s-rows [w*16, w*16+16).
//   smem: xs fp16 [128 s][256 c] swizzled (65536 B) | ts fp16 [32 h][136 s] (8704 B)
// ---------------------------------------------------------------------------
__global__ void __launch_bounds__(256) lnproj_kernel(
    const float* __restrict__ m1, const float* __restrict__ mask1,
    const float* __restrict__ ln1w, const float* __restrict__ ln1b,
    const float* __restrict__ b1,
    const float* __restrict__ m2, const float* __restrict__ mask2,
    const float* __restrict__ ln2w, const float* __restrict__ ln2b,
    const float* __restrict__ b2)
{
    extern __shared__ char psm[];
    const int blk = blockIdx.x;
    const int t = threadIdx.x;

    const int which = blk >> 8;
    const int i = blk & 255;
    const float* m    = which ? m2 : m1;
    const float* mask = which ? mask2 : mask1;
    const float* lnw  = which ? ln2w : ln1w;
    const float* lnb  = which ? ln2b : ln1b;
    const float* bias = which ? b2 : b1;

    __half* xs = (__half*)psm;                 // [128][256] swizzled, 512 B rows
    __half* ts = (__half*)(psm + 65536);       // [32][136]
    const int w = t >> 5, lane = t & 31;
    const int quad = lane >> 3, r8 = lane & 7;

    // ---- LN: 16 rows per warp -> xs fp16 (K-major, 16B-granule swizzle) ----
    const int c0 = lane * 8;
    float4 lw0 = *(const float4*)(lnw + c0);
    float4 lw1 = *(const float4*)(lnw + c0 + 4);
    float4 lb0 = *(const float4*)(lnb + c0);
    float4 lb1 = *(const float4*)(lnb + c0 + 4);
#pragma unroll 4
    for (int r = 0; r < 16; r++) {
        int s = w * 16 + r;
        const float* row = m + ((size_t)s * 256 + i) * CM;
        float4 v0 = *(const float4*)(row + c0);
        float4 v1 = *(const float4*)(row + c0 + 4);
        float sum = v0.x + v0.y + v0.z + v0.w + v1.x + v1.y + v1.z + v1.w;
#pragma unroll
        for (int o = 16; o; o >>= 1) sum += __shfl_xor_sync(0xffffffffu, sum, o);
        float mu = sum * (1.f / CM);
        float vs = (v0.x-mu)*(v0.x-mu) + (v0.y-mu)*(v0.y-mu) + (v0.z-mu)*(v0.z-mu)
                 + (v0.w-mu)*(v0.w-mu) + (v1.x-mu)*(v1.x-mu) + (v1.y-mu)*(v1.y-mu)
                 + (v1.z-mu)*(v1.z-mu) + (v1.w-mu)*(v1.w-mu);
#pragma unroll
        for (int o = 16; o; o >>= 1) vs += __shfl_xor_sync(0xffffffffu, vs, o);
        float rstd = rsqrtf(vs * (1.f / CM) + LN_EPS);
        __half2 h0, h1, h2v, h3;
        h0.x = __float2half_rn((v0.x - mu) * rstd * lw0.x + lb0.x);
        h0.y = __float2half_rn((v0.y - mu) * rstd * lw0.y + lb0.y);
        h1.x = __float2half_rn((v0.z - mu) * rstd * lw0.z + lb0.z);
        h1.y = __float2half_rn((v0.w - mu) * rstd * lw0.w + lb0.w);
        h2v.x = __float2half_rn((v1.x - mu) * rstd * lw1.x + lb1.x);
        h2v.y = __float2half_rn((v1.y - mu) * rstd * lw1.y + lb1.y);
        h3.x = __float2half_rn((v1.z - mu) * rstd * lw1.z + lb1.z);
        h3.y = __float2half_rn((v1.w - mu) * rstd * lw1.w + lb1.w);
        uint4 pk;
        pk.x = *(uint32_t*)&h0; pk.y = *(uint32_t*)&h1;
        pk.z = *(uint32_t*)&h2v; pk.w = *(uint32_t*)&h3;
        uint32_t off = (uint32_t)(s * 512 + ((lane * 16) ^ ((s & 7) << 4)));
        *(uint4*)((char*)xs + off) = pk;
    }
    __syncthreads();

    // ---- projection via mma: rows [w*16, w*16+16), n = 32 ----
    uint32_t sbx = smem_u32(xs);
    float acc[4][4];
#pragma unroll
    for (int a = 0; a < 4; a++)
#pragma unroll
        for (int b = 0; b < 4; b++) acc[a][b] = 0.f;

#pragma unroll
    for (int kt = 0; kt < 16; kt++) {
        int arow = w * 16 + (quad & 1) * 8 + r8;
        uint32_t akb = (uint32_t)(kt * 32 + (quad >> 1) * 16);
        uint32_t aoff = (uint32_t)(arow * 512) + (akb ^ ((uint32_t)(arow & 7) << 4));
        uint32_t a4[4];
        ldsm_x4(a4, sbx + aoff);
        uint4 wv0 = __ldg((const uint4*)gW12 + (which * 32 + kt * 2 + 0) * 32 + lane);
        uint4 wv1 = __ldg((const uint4*)gW12 + (which * 32 + kt * 2 + 1) * 32 + lane);
        uint32_t b0[2] = {wv0.x, wv0.y}, b1r[2] = {wv0.z, wv0.w};
        uint32_t b2r[2] = {wv1.x, wv1.y}, b3[2] = {wv1.z, wv1.w};
        mma_f16(acc[0], a4, b0);
        mma_f16(acc[1], a4, b1r);
        mma_f16(acc[2], a4, b2r);
        mma_f16(acc[3], a4, b3);
    }

    // ---- bias + mask, stage transpose ----
    {
        float mk0 = mask[(w * 16 + (lane >> 2)) * 256 + i];
        float mk1 = mask[(w * 16 + (lane >> 2) + 8) * 256 + i];
#pragma unroll
        for (int n8 = 0; n8 < 4; n8++) {
            int h = n8 * 8 + (lane & 3) * 2;
            float bh0 = __ldg(bias + h), bh1 = __ldg(bias + h + 1);
#pragma unroll
            for (int hh = 0; hh < 2; hh++) {
                int s = w * 16 + (lane >> 2) + hh * 8;
                float mk = hh ? mk1 : mk0;
                ts[h * 136 + s]       = __float2half_rn((acc[n8][hh * 2 + 0] + bh0) * mk);
                ts[(h + 1) * 136 + s] = __float2half_rn((acc[n8][hh * 2 + 1] + bh1) * mk);
            }
        }
    }
    __syncthreads();

    // ---- coalesced 16B stores: 512 stores over 256 threads (2 iters) ----
    {
        int h = t >> 3, g0 = t & 7;
        __half* dst = (which ? gBf : gAf);
#pragma unroll
        for (int r = 0; r < 2; r++) {
            int grp = g0 + r * 8;          // 0..15 -> s = grp*8..grp*8+7
            uint4 v = *(uint4*)((char*)ts + h * 272 + grp * 16);
            *(uint4*)&dst[((size_t)i * 32 + h) * 128 + grp * 8] = v;
        }
    }
}

// ---------------------------------------------------------------------------
// Mainloop blocks (fp16). K-chunk = 64 elems, SW128 tiles. 32 KB per chunk.
// ---------------------------------------------------------------------------
__device__ __forceinline__ void load_chunk_async(
    uint32_t sbuf, int m0, int n0, int k0, int t)
{
#pragma unroll
    for (int it = 0; it < 8; it++) {
        int id = it * 256 + t;
        int tile = id >> 10;
        int rem = id & 1023;
        int r = rem >> 3;
        int c8 = (rem & 7) * 8;
        const __half* src = (tile == 0)
            ? gAf + (size_t)(m0 + r) * 128 + k0 + c8
            : gBf + (size_t)(n0 + r) * 128 + k0 + c8;
        uint32_t off = (uint32_t)(r * 128 + c8 * 2);
        CP_ASYNC16(sbuf + tile * 16384 + SWZ128(off), src);
    }
}

__device__ __forceinline__ void compute_chunk(
    uint32_t sbuf, int wm0, int wn0, int lane, float (*acc)[4][4])
{
    const int quad = lane >> 3, r8 = lane & 7;
#pragma unroll
    for (int ks = 0; ks < 4; ks++) {
        const int kb = ks * 32;
        uint32_t a4[4][4];
#pragma unroll
        for (int mf = 0; mf < 4; mf++) {
            int row = wm0 + mf * 16 + (quad & 1) * 8 + r8;
            int kbyte = kb + (quad >> 1) * 16;
            ldsm_x4(a4[mf], sbuf + SWZ128((uint32_t)(row * 128 + kbyte)));
        }
        uint32_t b4[4][2];
#pragma unroll
        for (int nb = 0; nb < 2; nb++) {
            int row = wn0 + nb * 16 + (quad >> 1) * 8 + r8;
            int kbyte = kb + (quad & 1) * 16;
            uint32_t r4[4];
            ldsm_x4(r4, sbuf + 16384 + SWZ128((uint32_t)(row * 128 + kbyte)));
            b4[nb * 2][0] = r4[0]; b4[nb * 2][1] = r4[1];
            b4[nb * 2 + 1][0] = r4[2]; b4[nb * 2 + 1][1] = r4[3];
        }
#pragma unroll
        for (int mf = 0; mf < 4; mf++)
#pragma unroll
            for (int nf = 0; nf < 4; nf++)
                mma_f16(acc[mf][nf], a4[mf], b4[nf]);
    }
}

// ---------------------------------------------------------------------------
// Fused kernel (unchanged from R11). Dynamic smem 100352 B.
// ---------------------------------------------------------------------------
__global__ void __launch_bounds__(256, 2) fused_kernel(
    const float* __restrict__ b_out, float* __restrict__ out)
{
    extern __shared__ char dsm[];
    const int t = threadIdx.x, wid = t >> 5, lane = t & 31;
    const int bi = blockIdx.y, bj = blockIdx.x;
    const int m0 = bi * 128, n0 = bj * 128;
    const int wm0 = (wid >> 2) * 64, wn0 = (wid & 3) * 32;
    const int quad = lane >> 3, r8 = lane & 7;
    uint32_t sb = smem_u32(dsm);

    float acc[4][4][4];
#pragma unroll
    for (int a = 0; a < 4; a++)
#pragma unroll
        for (int b = 0; b < 4; b++)
#pragma unroll
            for (int c = 0; c < 4; c++) acc[a][b][c] = 0.f;

    load_chunk_async(sb, m0, n0, 0, t);
    load_chunk_async(sb + 32768, m0, n0, 64, t);
    CP_COMMIT();
    CP_WAIT(0);
    __syncthreads();
    compute_chunk(sb, wm0, wn0, lane, acc);
    compute_chunk(sb + 32768, wm0, wn0, lane, acc);
    __syncthreads();

#pragma unroll
    for (int mf = 0; mf < 4; mf++)
#pragma unroll
        for (int nf = 0; nf < 4; nf++)
#pragma unroll
            for (int half = 0; half < 2; half++) {
                int gm = wm0 + mf * 16 + (lane >> 2) + half * 8;
                int gn = wn0 + nf * 8 + (lane & 3) * 2;
                int p = ((gm >> 5) << 2) | (gn >> 5);
                int k = ((gm & 31) << 5) | (gn & 31);
                __half2 hp;
                hp.x = __float2half_rn(acc[mf][nf][half * 2 + 0]);
                hp.y = __float2half_rn(acc[mf][nf][half * 2 + 1]);
                uint32_t off = (uint32_t)(p * 2048 + ((k * 2) ^ ((p & 7) << 4)));
                *(__half2*)(dsm + off) = hp;
            }
    __syncthreads();

    float zacc[16][4];
#pragma unroll
    for (int a = 0; a < 16; a++)
#pragma unroll
        for (int b = 0; b < 4; b++) zacc[a][b] = 0.f;

#pragma unroll
    for (int kt = 0; kt < 8; kt++) {
        int arow = (quad & 1) * 8 + r8;
        uint32_t akb = (uint32_t)(wid * 256 + kt * 32 + (quad >> 1) * 16);
        uint32_t aoff = (uint32_t)(arow * 2048) + (akb ^ ((uint32_t)(arow & 7) << 4));
        uint32_t ah[4];
        ldsm_x4(ah, sb + aoff);
#pragma unroll
        for (int ntp = 0; ntp < 8; ntp++) {
            const uint4* wp = reinterpret_cast<const uint4*>(gWfrag)
                            + ((wid * 8 + kt) * 8 + ntp) * 32 + lane;
            uint4 bv = __ldg(wp);
            uint32_t b0[2] = {bv.x, bv.y}, b1[2] = {bv.z, bv.w};
            mma_f16(zacc[ntp * 2],     ah, b0);
            mma_f16(zacc[ntp * 2 + 1], ah, b1);
        }
    }

    {
        char* red = dsm + 32768 + wid * 8448;
#pragma unroll
        for (int nf = 0; nf < 16; nf++)
#pragma unroll
            for (int hh = 0; hh < 2; hh++) {
                int p = (lane >> 2) + hh * 8;
                int z = nf * 8 + (lane & 3) * 2;
                float2 v;
                v.x = zacc[nf][hh * 2 + 0];
                v.y = zacc[nf][hh * 2 + 1];
                *(float2*)(red + p * 528 + z * 4) = v;
            }
    }
    __syncthreads();

#pragma unroll
    for (int g2 = 0; g2 < 2; g2++) {
        int cell = t + g2 * 256;
        int p = cell >> 5;
        int z = (cell & 31) * 4;
        float4 s = {0.f, 0.f, 0.f, 0.f};
#pragma unroll
        for (int w = 0; w < 8; w++) {
            float4 v = *(float4*)(dsm + 32768 + w * 8448 + p * 528 + z * 4);
            s.x += v.x; s.y += v.y; s.z += v.z; s.w += v.w;
        }
        int i = bi * 4 + (p >> 2), j = bj * 4 + (p & 3);
        float invn = 1.f / g_norm[i * R_DIM + j];
        float4 bo = __ldg((const float4*)(b_out + z));
        float4 o;
        o.x = (s.x + bo.x) * invn;
        o.y = (s.y + bo.y) * invn;
        o.z = (s.z + bo.z) * invn;
        o.w = (s.w + bo.w) * invn;
        *(float4*)(out + ((size_t)i * R_DIM + j) * CZ + z) = o;
    }
}

// ---------------------------------------------------------------------------
extern "C" void kernel_launch(void* const* d_in, const int* in_sizes, int n_in,
                              void* d_out, int out_size)
{
    const float* m_1    = (const float*)d_in[0];
    const float* m_2    = (const float*)d_in[1];
    const float* mask_1 = (const float*)d_in[2];
    const float* mask_2 = (const float*)d_in[3];
    const float* ln1_w  = (const float*)d_in[4];
    const float* ln1_b  = (const float*)d_in[5];
    const float* ln2_w  = (const float*)d_in[6];
    const float* ln2_b  = (const float*)d_in[7];
    const float* w1     = (const float*)d_in[8];
    const float* b1     = (const float*)d_in[9];
    const float* w2     = (const float*)d_in[10];
    const float* b2     = (const float*)d_in[11];
    const float* w_out  = (const float*)d_in[12];
    const float* b_out  = (const float*)d_in[13];
    float* out = (float*)d_out;

    cudaFuncSetAttribute(lnproj_kernel,
                         cudaFuncAttributeMaxDynamicSharedMemorySize, 74240);
    cudaFuncSetAttribute(fused_kernel,
                         cudaFuncAttributeMaxDynamicSharedMemorySize, 100352);

    prep_kernel<<<256, 256>>>(mask_1, mask_2, w1, w2, w_out);
    lnproj_kernel<<<512, 256, 74240>>>(m_1, mask_1, ln1_w, ln1_b, b1,
                                       m_2, mask_2, ln2_w, ln2_b, b2);
    fused_kernel<<<dim3(64, 64), 256, 100352>>>(b_out, out);
}

// round 14
// speedup vs baseline: 18.3613x; 1.0371x over previous
#include <cuda_runtime.h>
#include <cuda_bf16.h>
#include <cuda_fp16.h>
#include <cstdint>

#define S_DIM 128
#define R_DIM 256
#define CM    256
#define H_DIM 32
#define CZ    128
#define LN_EPS 1e-5f
#define EPS_N  1e-3f

// GEMM1 operands: [8192, 128] fp16, row-major (m=(i*32+h), k=s)
__device__ __half gAf[8192 * 128];
__device__ __half gBf[8192 * 128];
// w_out in mma-B-fragment order (see R11): 131072 uint32
__device__ uint32_t gWfrag[131072];
// w1/w2 in mma-B-fragment order: u = which*4096 + kt*256 + ntp*128 + lane*4 + r2
__device__ uint32_t gW12[8192];
__device__ float g_norm[R_DIM * R_DIM];

// ---------------------------------------------------------------------------
__device__ __forceinline__ uint32_t smem_u32(const void* p) {
    uint32_t a;
    asm("{ .reg .u64 t; cvta.to.shared.u64 t, %1; cvt.u32.u64 %0, t; }" : "=r"(a) : "l"(p));
    return a;
}
#define SWZ128(o) ((o) ^ (((o) >> 3) & 0x70))
#define CP_ASYNC16(dst, src) asm volatile("cp.async.cg.shared.global [%0], [%1], 16;" :: "r"(dst), "l"(src))
#define CP_COMMIT()          asm volatile("cp.async.commit_group;" ::: "memory")
#define CP_WAIT(n)           asm volatile("cp.async.wait_group %0;" :: "n"(n) : "memory")

__device__ __forceinline__ void ldsm_x4(uint32_t* r, uint32_t addr) {
    asm volatile("ldmatrix.sync.aligned.m8n8.x4.shared.b16 {%0,%1,%2,%3}, [%4];"
                 : "=r"(r[0]), "=r"(r[1]), "=r"(r[2]), "=r"(r[3]) : "r"(addr));
}
__device__ __forceinline__ void mma_f16(float* d, const uint32_t* a, const uint32_t* b) {
    asm volatile(
        "mma.sync.aligned.m16n8k16.row.col.f32.f16.f16.f32 "
        "{%0,%1,%2,%3}, {%4,%5,%6,%7}, {%8,%9}, {%0,%1,%2,%3};"
        : "+f"(d[0]), "+f"(d[1]), "+f"(d[2]), "+f"(d[3])
        : "r"(a[0]), "r"(a[1]), "r"(a[2]), "r"(a[3]),
          "r"(b[0]), "r"(b[1]));
}
__device__ __forceinline__ uint32_t pack_h2(float lo, float hi) {
    __half2 h;
    h.x = __float2half_rn(lo);
    h.y = __float2half_rn(hi);
    return *(uint32_t*)&h;
}

// ---------------------------------------------------------------------------
// Prep kernel (runs FIRST): gW12 packing only. 2 blocks (which = blockIdx.x).
// Stages w1/w2 (256x32 fp32) through smem coalesced, packs from smem.
// ---------------------------------------------------------------------------
__global__ void __launch_bounds__(256) prep_kernel(
    const float* __restrict__ w1, const float* __restrict__ w2)
{
    __shared__ float ws[CM * H_DIM];    // 32 KB
    const int which = blockIdx.x;
    const int t = threadIdx.x;
    const float* wsrc = which ? w2 : w1;

#pragma unroll
    for (int r = 0; r < 32; r++)
        ws[t + r * 256] = wsrc[t + r * 256];
    __syncthreads();

#pragma unroll
    for (int r = 0; r < 16; r++) {
        int u2 = r * 256 + t;
        int r2 = u2 & 3;
        int lane = (u2 >> 2) & 31;
        int ntp = (u2 >> 7) & 1;
        int kt = u2 >> 8;
        int ntsub = r2 >> 1, rr = r2 & 1;
        int k = kt * 16 + (lane & 3) * 2 + rr * 8;
        int n = (ntp * 2 + ntsub) * 8 + (lane >> 2);
        unsigned short lo = __half_as_ushort(__float2half_rn(ws[k * H_DIM + n]));
        unsigned short hi = __half_as_ushort(__float2half_rn(ws[(k + 1) * H_DIM + n]));
        gW12[which * 4096 + u2] = (uint32_t)lo | ((uint32_t)hi << 16);
    }
}

// ---------------------------------------------------------------------------
// LN + projection kernel, 832 blocks:
//   [0,512):   LN + tensor-core projection (which=blk>>8, i=blk&255)
//   [512,768): norm matrix row i = blk-512
//   [768,832): gWfrag packing, ktg = blk-768 (smem-staged, uint4 stores)
// Dynamic smem 74240 B (LN blocks use all; others use a prefix).
// ---------------------------------------------------------------------------
__global__ void __launch_bounds__(256) lnproj_kernel(
    const float* __restrict__ m1, const float* __restrict__ mask1,
    const float* __restrict__ ln1w, const float* __restrict__ ln1b,
    const float* __restrict__ b1,
    const float* __restrict__ m2, const float* __restrict__ mask2,
    const float* __restrict__ ln2w, const float* __restrict__ ln2b,
    const float* __restrict__ b2,
    const float* __restrict__ w_out)
{
    extern __shared__ char psm[];
    const int blk = blockIdx.x;
    const int t = threadIdx.x;

    if (blk >= 768) {
        // ---- gWfrag packing: ktg covers k in [ktg*16, ktg*16+16) ----
        const int ktg = blk - 768;
        float* ws = (float*)psm;                  // [16][128]
#pragma unroll
        for (int r = 0; r < 8; r++) {
            int idx = t + r * 256;                // 2048 floats
            int kk = idx >> 7, n = idx & 127;
            ws[idx] = w_out[(ktg * 16 + kk) * CZ + n];
        }
        __syncthreads();
        const int lane = t & 31, ntp = t >> 5;
        uint32_t pk[4];
#pragma unroll
        for (int r2 = 0; r2 < 4; r2++) {
            int ntsub = r2 >> 1, rr = r2 & 1;
            int kk = (lane & 3) * 2 + rr * 8;
            int n = (ntp * 2 + ntsub) * 8 + (lane >> 2);
            pk[r2] = pack_h2(ws[kk * 128 + n], ws[(kk + 1) * 128 + n]);
        }
        *(uint4*)&gWfrag[ktg * 1024 + t * 4] = *(uint4*)pk;
        return;
    }
    if (blk >= 512) {
        // ---- norm row ----
        const int i = blk - 512, j = t;
        float sum = 0.f;
#pragma unroll 4
        for (int s = 0; s < S_DIM; s++)
            sum += mask1[s * R_DIM + i] * mask2[s * R_DIM + j];
        g_norm[i * R_DIM + j] = sum + EPS_N;
        return;
    }

    // ---- LN + tensor-core projection ----
    const int which = blk >> 8;
    const int i = blk & 255;
    const float* m    = which ? m2 : m1;
    const float* mask = which ? mask2 : mask1;
    const float* lnw  = which ? ln2w : ln1w;
    const float* lnb  = which ? ln2b : ln1b;
    const float* bias = which ? b2 : b1;

    __half* xs = (__half*)psm;                 // [128][256] swizzled, 512 B rows
    __half* ts = (__half*)(psm + 65536);       // [32][136]
    const int w = t >> 5, lane = t & 31;
    const int quad = lane >> 3, r8 = lane & 7;

    const int c0 = lane * 8;
    float4 lw0 = *(const float4*)(lnw + c0);
    float4 lw1 = *(const float4*)(lnw + c0 + 4);
    float4 lb0 = *(const float4*)(lnb + c0);
    float4 lb1 = *(const float4*)(lnb + c0 + 4);
#pragma unroll 4
    for (int r = 0; r < 16; r++) {
        int s = w * 16 + r;
        const float* row = m + ((size_t)s * 256 + i) * CM;
        float4 v0 = *(const float4*)(row + c0);
        float4 v1 = *(const float4*)(row + c0 + 4);
        float sum = v0.x + v0.y + v0.z + v0.w + v1.x + v1.y + v1.z + v1.w;
#pragma unroll
        for (int o = 16; o; o >>= 1) sum += __shfl_xor_sync(0xffffffffu, sum, o);
        float mu = sum * (1.f / CM);
        float vs = (v0.x-mu)*(v0.x-mu) + (v0.y-mu)*(v0.y-mu) + (v0.z-mu)*(v0.z-mu)
                 + (v0.w-mu)*(v0.w-mu) + (v1.x-mu)*(v1.x-mu) + (v1.y-mu)*(v1.y-mu)
                 + (v1.z-mu)*(v1.z-mu) + (v1.w-mu)*(v1.w-mu);
#pragma unroll
        for (int o = 16; o; o >>= 1) vs += __shfl_xor_sync(0xffffffffu, vs, o);
        float rstd = rsqrtf(vs * (1.f / CM) + LN_EPS);
        uint4 pk;
        pk.x = pack_h2((v0.x - mu) * rstd * lw0.x + lb0.x,
                       (v0.y - mu) * rstd * lw0.y + lb0.y);
        pk.y = pack_h2((v0.z - mu) * rstd * lw0.z + lb0.z,
                       (v0.w - mu) * rstd * lw0.w + lb0.w);
        pk.z = pack_h2((v1.x - mu) * rstd * lw1.x + lb1.x,
                       (v1.y - mu) * rstd * lw1.y + lb1.y);
        pk.w = pack_h2((v1.z - mu) * rstd * lw1.z + lb1.z,
                       (v1.w - mu) * rstd * lw1.w + lb1.w);
        uint32_t off = (uint32_t)(s * 512 + ((lane * 16) ^ ((s & 7) << 4)));
        *(uint4*)((char*)xs + off) = pk;
    }
    __syncthreads();

    uint32_t sbx = smem_u32(xs);
    float acc[4][4];
#pragma unroll
    for (int a = 0; a < 4; a++)
#pragma unroll
        for (int b = 0; b < 4; b++) acc[a][b] = 0.f;

#pragma unroll
    for (int kt = 0; kt < 16; kt++) {
        int arow = w * 16 + (quad & 1) * 8 + r8;
        uint32_t akb = (uint32_t)(kt * 32 + (quad >> 1) * 16);
        uint32_t aoff = (uint32_t)(arow * 512) + (akb ^ ((uint32_t)(arow & 7) << 4));
        uint32_t a4[4];
        ldsm_x4(a4, sbx + aoff);
        uint4 wv0 = __ldg((const uint4*)gW12 + (which * 32 + kt * 2 + 0) * 32 + lane);
        uint4 wv1 = __ldg((const uint4*)gW12 + (which * 32 + kt * 2 + 1) * 32 + lane);
        uint32_t b0[2] = {wv0.x, wv0.y}, b1r[2] = {wv0.z, wv0.w};
        uint32_t b2r[2] = {wv1.x, wv1.y}, b3[2] = {wv1.z, wv1.w};
        mma_f16(acc[0], a4, b0);
        mma_f16(acc[1], a4, b1r);
        mma_f16(acc[2], a4, b2r);
        mma_f16(acc[3], a4, b3);
    }

    {
        float mk0 = mask[(w * 16 + (lane >> 2)) * 256 + i];
        float mk1 = mask[(w * 16 + (lane >> 2) + 8) * 256 + i];
#pragma unroll
        for (int n8 = 0; n8 < 4; n8++) {
            int h = n8 * 8 + (lane & 3) * 2;
            float bh0 = __ldg(bias + h), bh1 = __ldg(bias + h + 1);
#pragma unroll
            for (int hh = 0; hh < 2; hh++) {
                int s = w * 16 + (lane >> 2) + hh * 8;
                float mk = hh ? mk1 : mk0;
                ts[h * 136 + s]       = __float2half_rn((acc[n8][hh * 2 + 0] + bh0) * mk);
                ts[(h + 1) * 136 + s] = __float2half_rn((acc[n8][hh * 2 + 1] + bh1) * mk);
            }
        }
    }
    __syncthreads();

    {
        int h = t >> 3, g0 = t & 7;
        __half* dst = (which ? gBf : gAf);
#pragma unroll
        for (int r = 0; r < 2; r++) {
            int grp = g0 + r * 8;
            uint4 v = *(uint4*)((char*)ts + h * 272 + grp * 16);
            *(uint4*)&dst[((size_t)i * 32 + h) * 128 + grp * 8] = v;
        }
    }
}

// ---------------------------------------------------------------------------
// Mainloop blocks (fp16). K-chunk = 64 elems, SW128 tiles. 32 KB per chunk.
// ---------------------------------------------------------------------------
__device__ __forceinline__ void load_chunk_async(
    uint32_t sbuf, int m0, int n0, int k0, int t)
{
#pragma unroll
    for (int it = 0; it < 8; it++) {
        int id = it * 256 + t;
        int tile = id >> 10;
        int rem = id & 1023;
        int r = rem >> 3;
        int c8 = (rem & 7) * 8;
        const __half* src = (tile == 0)
            ? gAf + (size_t)(m0 + r) * 128 + k0 + c8
            : gBf + (size_t)(n0 + r) * 128 + k0 + c8;
        uint32_t off = (uint32_t)(r * 128 + c8 * 2);
        CP_ASYNC16(sbuf + tile * 16384 + SWZ128(off), src);
    }
}

__device__ __forceinline__ void compute_chunk(
    uint32_t sbuf, int wm0, int wn0, int lane, float (*acc)[4][4])
{
    const int quad = lane >> 3, r8 = lane & 7;
#pragma unroll
    for (int ks = 0; ks < 4; ks++) {
        const int kb = ks * 32;
        uint32_t a4[4][4];
#pragma unroll
        for (int mf = 0; mf < 4; mf++) {
            int row = wm0 + mf * 16 + (quad & 1) * 8 + r8;
            int kbyte = kb + (quad >> 1) * 16;
            ldsm_x4(a4[mf], sbuf + SWZ128((uint32_t)(row * 128 + kbyte)));
        }
        uint32_t b4[4][2];
#pragma unroll
        for (int nb = 0; nb < 2; nb++) {
            int row = wn0 + nb * 16 + (quad >> 1) * 8 + r8;
            int kbyte = kb + (quad & 1) * 16;
            uint32_t r4[4];
            ldsm_x4(r4, sbuf + 16384 + SWZ128((uint32_t)(row * 128 + kbyte)));
            b4[nb * 2][0] = r4[0]; b4[nb * 2][1] = r4[1];
            b4[nb * 2 + 1][0] = r4[2]; b4[nb * 2 + 1][1] = r4[3];
        }
#pragma unroll
        for (int mf = 0; mf < 4; mf++)
#pragma unroll
            for (int nf = 0; nf < 4; nf++)
                mma_f16(acc[mf][nf], a4[mf], b4[nf]);
    }
}

// ---------------------------------------------------------------------------
// Fused kernel (unchanged). Dynamic smem 100352 B.
// ---------------------------------------------------------------------------
__global__ void __launch_bounds__(256, 2) fused_kernel(
    const float* __restrict__ b_out, float* __restrict__ out)
{
    extern __shared__ char dsm[];
    const int t = threadIdx.x, wid = t >> 5, lane = t & 31;
    const int bi = blockIdx.y, bj = blockIdx.x;
    const int m0 = bi * 128, n0 = bj * 128;
    const int wm0 = (wid >> 2) * 64, wn0 = (wid & 3) * 32;
    const int quad = lane >> 3, r8 = lane & 7;
    uint32_t sb = smem_u32(dsm);

    float acc[4][4][4];
#pragma unroll
    for (int a = 0; a < 4; a++)
#pragma unroll
        for (int b = 0; b < 4; b++)
#pragma unroll
            for (int c = 0; c < 4; c++) acc[a][b][c] = 0.f;

    load_chunk_async(sb, m0, n0, 0, t);
    load_chunk_async(sb + 32768, m0, n0, 64, t);
    CP_COMMIT();
    CP_WAIT(0);
    __syncthreads();
    compute_chunk(sb, wm0, wn0, lane, acc);
    compute_chunk(sb + 32768, wm0, wn0, lane, acc);
    __syncthreads();

#pragma unroll
    for (int mf = 0; mf < 4; mf++)
#pragma unroll
        for (int nf = 0; nf < 4; nf++)
#pragma unroll
            for (int half = 0; half < 2; half++) {
                int gm = wm0 + mf * 16 + (lane >> 2) + half * 8;
                int gn = wn0 + nf * 8 + (lane & 3) * 2;
                int p = ((gm >> 5) << 2) | (gn >> 5);
                int k = ((gm & 31) << 5) | (gn & 31);
                __half2 hp;
                hp.x = __float2half_rn(acc[mf][nf][half * 2 + 0]);
                hp.y = __float2half_rn(acc[mf][nf][half * 2 + 1]);
                uint32_t off = (uint32_t)(p * 2048 + ((k * 2) ^ ((p & 7) << 4)));
                *(__half2*)(dsm + off) = hp;
            }
    __syncthreads();

    float zacc[16][4];
#pragma unroll
    for (int a = 0; a < 16; a++)
#pragma unroll
        for (int b = 0; b < 4; b++) zacc[a][b] = 0.f;

#pragma unroll
    for (int kt = 0; kt < 8; kt++) {
        int arow = (quad & 1) * 8 + r8;
        uint32_t akb = (uint32_t)(wid * 256 + kt * 32 + (quad >> 1) * 16);
        uint32_t aoff = (uint32_t)(arow * 2048) + (akb ^ ((uint32_t)(arow & 7) << 4));
        uint32_t ah[4];
        ldsm_x4(ah, sb + aoff);
#pragma unroll
        for (int ntp = 0; ntp < 8; ntp++) {
            const uint4* wp = reinterpret_cast<const uint4*>(gWfrag)
                            + ((wid * 8 + kt) * 8 + ntp) * 32 + lane;
            uint4 bv = __ldg(wp);
            uint32_t b0[2] = {bv.x, bv.y}, b1[2] = {bv.z, bv.w};
            mma_f16(zacc[ntp * 2],     ah, b0);
            mma_f16(zacc[ntp * 2 + 1], ah, b1);
        }
    }

    {
        char* red = dsm + 32768 + wid * 8448;
#pragma unroll
        for (int nf = 0; nf < 16; nf++)
#pragma unroll
            for (int hh = 0; hh < 2; hh++) {
                int p = (lane >> 2) + hh * 8;
                int z = nf * 8 + (lane & 3) * 2;
                float2 v;
                v.x = zacc[nf][hh * 2 + 0];
                v.y = zacc[nf][hh * 2 + 1];
                *(float2*)(red + p * 528 + z * 4) = v;
            }
    }
    __syncthreads();

#pragma unroll
    for (int g2 = 0; g2 < 2; g2++) {
        int cell = t + g2 * 256;
        int p = cell >> 5;
        int z = (cell & 31) * 4;
        float4 s = {0.f, 0.f, 0.f, 0.f};
#pragma unroll
        for (int w = 0; w < 8; w++) {
            float4 v = *(float4*)(dsm + 32768 + w * 8448 + p * 528 + z * 4);
            s.x += v.x; s.y += v.y; s.z += v.z; s.w += v.w;
        }
        int i = bi * 4 + (p >> 2), j = bj * 4 + (p & 3);
        float invn = 1.f / g_norm[i * R_DIM + j];
        float4 bo = __ldg((const float4*)(b_out + z));
        float4 o;
        o.x = (s.x + bo.x) * invn;
        o.y = (s.y + bo.y) * invn;
        o.z = (s.z + bo.z) * invn;
        o.w = (s.w + bo.w) * invn;
        *(float4*)(out + ((size_t)i * R_DIM + j) * CZ + z) = o;
    }
}

// ---------------------------------------------------------------------------
extern "C" void kernel_launch(void* const* d_in, const int* in_sizes, int n_in,
                              void* d_out, int out_size)
{
    const float* m_1    = (const float*)d_in[0];
    const float* m_2    = (const float*)d_in[1];
    const float* mask_1 = (const float*)d_in[2];
    const float* mask_2 = (const float*)d_in[3];
    const float* ln1_w  = (const float*)d_in[4];
    const float* ln1_b  = (const float*)d_in[5];
    const float* ln2_w  = (const float*)d_in[6];
    const float* ln2_b  = (const float*)d_in[7];
    const float* w1     = (const float*)d_in[8];
    const float* b1     = (const float*)d_in[9];
    const float* w2     = (const float*)d_in[10];
    const float* b2     = (const float*)d_in[11];
    const float* w_out  = (const float*)d_in[12];
    const float* b_out  = (const float*)d_in[13];
    float* out = (float*)d_out;

    cudaFuncSetAttribute(lnproj_kernel,
                         cudaFuncAttributeMaxDynamicSharedMemorySize, 74240);
    cudaFuncSetAttribute(fused_kernel,
                         cudaFuncAttributeMaxDynamicSharedMemorySize, 100352);

    prep_kernel<<<2, 256>>>(w1, w2);
    lnproj_kernel<<<832, 256, 74240>>>(m_1, mask_1, ln1_w, ln1_b, b1,
                                       m_2, mask_2, ln2_w, ln2_b, b2, w_out);
    fused_kernel<<<dim3(64, 64), 256, 100352>>>(b_out, out);
}